// round 1
// baseline (speedup 1.0000x reference)
#include <cuda_runtime.h>
#include <math.h>

#define NHID 64
#define NMAX 400000
#define NXMAX 100000
#define BN_EPS 1e-5f

// ---------------- scratch (device globals; no allocations) ----------------
__device__ float  g_dn[NMAX];
__device__ float  g_de[NMAX];
__device__ float  g_h [NMAX * NHID];
__device__ float  g_mn[NMAX * NHID];
__device__ float  g_me[NMAX * NHID];
__device__ float  g_t [NXMAX * NHID];
__device__ double g_sum[NHID];
__device__ double g_sumsq[NHID];

// ---------------- K0: zero scratch ----------------
__global__ void k_zero(int n4, int N) {
    int i = blockIdx.x * blockDim.x + threadIdx.x;
    int stride = gridDim.x * blockDim.x;
    float4 z = make_float4(0.f, 0.f, 0.f, 0.f);
    float4* mn4 = reinterpret_cast<float4*>(g_mn);
    float4* me4 = reinterpret_cast<float4*>(g_me);
    for (int j = i; j < n4; j += stride) { mn4[j] = z; me4[j] = z; }
    for (int j = i; j < N; j += stride) { g_dn[j] = 0.f; g_de[j] = 0.f; }
    if (i < NHID) { g_sum[i] = 0.0; g_sumsq[i] = 0.0; }
}

// ---------------- K1: diagonal extraction ----------------
__global__ void k_diag(const int* __restrict__ nr, const int* __restrict__ nc,
                       const float* __restrict__ nv, int nnzN,
                       const int* __restrict__ er, const int* __restrict__ ec,
                       const float* __restrict__ ev, int nnzE) {
    int i = blockIdx.x * blockDim.x + threadIdx.x;
    int stride = gridDim.x * blockDim.x;
    int tot = nnzN + nnzE;
    for (int j = i; j < tot; j += stride) {
        if (j < nnzN) {
            int r = nr[j], c = nc[j];
            if (r == c) atomicAdd(&g_dn[r], nv[j]);
        } else {
            int e = j - nnzN;
            int r = er[e], c = ec[e];
            if (r == c) atomicAdd(&g_de[r], ev[e]);
        }
    }
}

// ---------------- K2: copy h_in into g_h[0..Nold) ----------------
__global__ void k_copy_h(const float4* __restrict__ src, int n4) {
    int i = blockIdx.x * blockDim.x + threadIdx.x;
    int stride = gridDim.x * blockDim.x;
    float4* dst = reinterpret_cast<float4*>(g_h);
    for (int j = i; j < n4; j += stride) dst[j] = src[j];
}

// ---------------- K3: lin1 + BN stats ----------------
// block = 256 threads = 4 rows x 64 outputs
__global__ void k_lin1(const float* __restrict__ x, const float* __restrict__ W1,
                       const float* __restrict__ b1, int Nx) {
    __shared__ float sW[NHID * NHID];
    __shared__ float sP[NHID], sPq[NHID];
    int tid = threadIdx.x;
    for (int t = tid; t < NHID * NHID; t += blockDim.x) sW[t] = W1[t];
    if (tid < NHID) { sP[tid] = 0.f; sPq[tid] = 0.f; }
    __syncthreads();
    int row = blockIdx.x * 4 + tid / NHID;
    int j = tid & (NHID - 1);
    if (row < Nx) {
        const float* xr = x + row * NHID;
        float acc = b1[j];
        const float* wr = sW + j * NHID;
#pragma unroll
        for (int k = 0; k < NHID; k++) acc += xr[k] * wr[k];
        g_t[row * NHID + j] = acc;
        atomicAdd(&sP[j], acc);
        atomicAdd(&sPq[j], acc * acc);
    }
    __syncthreads();
    if (tid < NHID) {
        atomicAdd(&g_sum[tid], (double)sP[tid]);
        atomicAdd(&g_sumsq[tid], (double)sPq[tid]);
    }
}

// ---------------- K4: BN + ReLU + lin2 + h_update ----------------
__global__ void k_lin2(const float* __restrict__ gamma, const float* __restrict__ beta,
                       const float* __restrict__ W2, const float* __restrict__ b2,
                       int Nx, int Nold) {
    __shared__ float sW[NHID * NHID];
    __shared__ float sScale[NHID], sShift[NHID];
    int tid = threadIdx.x;
    for (int t = tid; t < NHID * NHID; t += blockDim.x) sW[t] = W2[t];
    if (tid < NHID) {
        double mu = g_sum[tid] / (double)Nx;
        double var = g_sumsq[tid] / (double)Nx - mu * mu;
        float inv = rsqrtf((float)var + BN_EPS);
        float sc = gamma[tid] * inv;
        sScale[tid] = sc;
        sShift[tid] = beta[tid] - (float)mu * sc;
    }
    __syncthreads();
    int row = blockIdx.x * 4 + tid / NHID;
    int j = tid & (NHID - 1);
    if (row < Nx) {
        const float* tr = g_t + row * NHID;
        float acc = b2[j];
        const float* wr = sW + j * NHID;
#pragma unroll
        for (int k = 0; k < NHID; k++) {
            float v = tr[k] * sScale[k] + sShift[k];
            v = fmaxf(v, 0.f);
            acc += v * wr[k];
        }
        acc *= g_dn[Nold + row];
        g_h[(Nold + row) * NHID + j] = acc;
    }
}

// ---------------- K5: spmm (off-diagonal), warp per entry ----------------
__global__ void k_spmm(const int* __restrict__ nr, const int* __restrict__ nc,
                       const float* __restrict__ nv, int nnzN,
                       const int* __restrict__ er, const int* __restrict__ ec,
                       const float* __restrict__ ev, int nnzE) {
    int wid = (blockIdx.x * blockDim.x + threadIdx.x) >> 5;
    int lane = threadIdx.x & 31;
    int tot = nnzN + nnzE;
    if (wid >= tot) return;
    int r, c; float v; float* M;
    if (wid < nnzN) {
        r = nr[wid]; c = nc[wid];
        if (r == c) return;
        v = nv[wid]; M = g_mn;
    } else {
        int e = wid - nnzN;
        r = er[e]; c = ec[e];
        if (r == c) return;
        v = ev[e]; M = g_me;
    }
    float2 hv = reinterpret_cast<const float2*>(g_h + c * NHID)[lane];
    atomicAdd(&M[r * NHID + 2 * lane],     v * hv.x);
    atomicAdd(&M[r * NHID + 2 * lane + 1], v * hv.y);
}

// ---------------- K6: fused dual-GRU + output heads ----------------
// dynamic shared: Wi(192*64) Wh(192*64) bi(192) bh(192) won(64) woe(64)
#define SM_WI 0
#define SM_WH (192 * 64)
#define SM_BI (2 * 192 * 64)
#define SM_BH (SM_BI + 192)
#define SM_WON (SM_BH + 192)
#define SM_WOE (SM_WON + 64)
#define SM_FLOATS (SM_WOE + 64)

__device__ __forceinline__ float sigmf(float x) { return 1.0f / (1.0f + expf(-x)); }

__global__ void __launch_bounds__(128) k_gru(
    const float* __restrict__ Wi_n, const float* __restrict__ bi_n,
    const float* __restrict__ Wh_n, const float* __restrict__ bh_n,
    const float* __restrict__ Wi_e, const float* __restrict__ bi_e,
    const float* __restrict__ Wh_e, const float* __restrict__ bh_e,
    const float* __restrict__ w_on, const float* __restrict__ b_on,
    const float* __restrict__ w_oe, const float* __restrict__ b_oe,
    int N, float* __restrict__ out) {
    extern __shared__ float sm[];
    float* sWi = sm + SM_WI;
    float* sWh = sm + SM_WH;
    float* sBi = sm + SM_BI;
    float* sBh = sm + SM_BH;
    float* sWon = sm + SM_WON;
    float* sWoe = sm + SM_WOE;
    int tid = threadIdx.x;
    int i = blockIdx.x * blockDim.x + tid;
    bool active = i < N;

    float m[NHID], hreg[NHID];
    float dn_i = 0.f, de_i = 0.f;
    if (active) {
        dn_i = g_dn[i];
        de_i = g_de[i];
        const float4* h4 = reinterpret_cast<const float4*>(g_h + i * NHID);
        const float4* m4 = reinterpret_cast<const float4*>(g_mn + i * NHID);
#pragma unroll
        for (int k = 0; k < 16; k++) {
            float4 a = h4[k]; hreg[4*k] = a.x; hreg[4*k+1] = a.y; hreg[4*k+2] = a.z; hreg[4*k+3] = a.w;
            float4 b = m4[k]; m[4*k] = b.x; m[4*k+1] = b.y; m[4*k+2] = b.z; m[4*k+3] = b.w;
        }
    }
    float* out_h = out + 2 * (size_t)N;

    // ---- phase 1: node GRU ----
    for (int t = tid; t < 192 * 64; t += blockDim.x) { sWi[t] = Wi_n[t]; sWh[t] = Wh_n[t]; }
    for (int t = tid; t < 192; t += blockDim.x) { sBi[t] = bi_n[t]; sBh[t] = bh_n[t]; }
    if (tid < 64) { sWon[tid] = w_on[tid]; sWoe[tid] = w_oe[tid]; }
    __syncthreads();
    if (active) {
        for (int j = 0; j < NHID; j++) {
            float ir = sBi[j], iz = sBi[64 + j], in_ = sBi[128 + j];
            float hr = sBh[j], hz = sBh[64 + j], hn = sBh[128 + j];
            const float4* w0 = reinterpret_cast<const float4*>(sWi + j * 64);
            const float4* w1 = reinterpret_cast<const float4*>(sWi + (64 + j) * 64);
            const float4* w2 = reinterpret_cast<const float4*>(sWi + (128 + j) * 64);
            const float4* v0 = reinterpret_cast<const float4*>(sWh + j * 64);
            const float4* v1 = reinterpret_cast<const float4*>(sWh + (64 + j) * 64);
            const float4* v2 = reinterpret_cast<const float4*>(sWh + (128 + j) * 64);
#pragma unroll
            for (int kk = 0; kk < 16; kk++) {
                float a0 = m[4*kk], a1 = m[4*kk+1], a2 = m[4*kk+2], a3 = m[4*kk+3];
                float b0 = hreg[4*kk], b1 = hreg[4*kk+1], b2 = hreg[4*kk+2], b3 = hreg[4*kk+3];
                float4 W0 = w0[kk]; ir += a0*W0.x + a1*W0.y + a2*W0.z + a3*W0.w;
                float4 W1 = w1[kk]; iz += a0*W1.x + a1*W1.y + a2*W1.z + a3*W1.w;
                float4 W2 = w2[kk]; in_ += a0*W2.x + a1*W2.y + a2*W2.z + a3*W2.w;
                float4 V0 = v0[kk]; hr += b0*V0.x + b1*V0.y + b2*V0.z + b3*V0.w;
                float4 V1 = v1[kk]; hz += b0*V1.x + b1*V1.y + b2*V1.z + b3*V1.w;
                float4 V2 = v2[kk]; hn += b0*V2.x + b1*V2.y + b2*V2.z + b3*V2.w;
            }
            float r = sigmf(ir + hr);
            float z = sigmf(iz + hz);
            float ng = tanhf(in_ + r * hn);
            float hv = (1.f - z) * ng + z * hreg[j];
            out_h[(size_t)i * NHID + j] = dn_i * hv;   // partial
        }
    }
    __syncthreads();

    // ---- phase 2: edge GRU + combine + heads ----
    for (int t = tid; t < 192 * 64; t += blockDim.x) { sWi[t] = Wi_e[t]; sWh[t] = Wh_e[t]; }
    for (int t = tid; t < 192; t += blockDim.x) { sBi[t] = bi_e[t]; sBh[t] = bh_e[t]; }
    __syncthreads();
    if (active) {
        const float4* m4 = reinterpret_cast<const float4*>(g_me + i * NHID);
#pragma unroll
        for (int k = 0; k < 16; k++) {
            float4 b = m4[k]; m[4*k] = b.x; m[4*k+1] = b.y; m[4*k+2] = b.z; m[4*k+3] = b.w;
        }
        float s_on = 0.f, s_oe = 0.f;
        for (int j = 0; j < NHID; j++) {
            float ir = sBi[j], iz = sBi[64 + j], in_ = sBi[128 + j];
            float hr = sBh[j], hz = sBh[64 + j], hn = sBh[128 + j];
            const float4* w0 = reinterpret_cast<const float4*>(sWi + j * 64);
            const float4* w1 = reinterpret_cast<const float4*>(sWi + (64 + j) * 64);
            const float4* w2 = reinterpret_cast<const float4*>(sWi + (128 + j) * 64);
            const float4* v0 = reinterpret_cast<const float4*>(sWh + j * 64);
            const float4* v1 = reinterpret_cast<const float4*>(sWh + (64 + j) * 64);
            const float4* v2 = reinterpret_cast<const float4*>(sWh + (128 + j) * 64);
#pragma unroll
            for (int kk = 0; kk < 16; kk++) {
                float a0 = m[4*kk], a1 = m[4*kk+1], a2 = m[4*kk+2], a3 = m[4*kk+3];
                float b0 = hreg[4*kk], b1 = hreg[4*kk+1], b2 = hreg[4*kk+2], b3 = hreg[4*kk+3];
                float4 W0 = w0[kk]; ir += a0*W0.x + a1*W0.y + a2*W0.z + a3*W0.w;
                float4 W1 = w1[kk]; iz += a0*W1.x + a1*W1.y + a2*W1.z + a3*W1.w;
                float4 W2 = w2[kk]; in_ += a0*W2.x + a1*W2.y + a2*W2.z + a3*W2.w;
                float4 V0 = v0[kk]; hr += b0*V0.x + b1*V0.y + b2*V0.z + b3*V0.w;
                float4 V1 = v1[kk]; hz += b0*V1.x + b1*V1.y + b2*V1.z + b3*V1.w;
                float4 V2 = v2[kk]; hn += b0*V2.x + b1*V2.y + b2*V2.z + b3*V2.w;
            }
            float r = sigmf(ir + hr);
            float z = sigmf(iz + hz);
            float ng = tanhf(in_ + r * hn);
            float hv = (1.f - z) * ng + z * hreg[j];
            size_t oi = (size_t)i * NHID + j;
            float hf = out_h[oi] + de_i * hv;
            out_h[oi] = hf;
            s_on += hf * sWon[j];
            s_oe += hf * sWoe[j];
        }
        float y = dn_i * (s_on + b_on[0]) + de_i * (s_oe + b_oe[0]);
        out[i] = sigmf(y);
        out[(size_t)N + i] = y;
    }
}

// ---------------- launch ----------------
extern "C" void kernel_launch(void* const* d_in, const int* in_sizes, int n_in,
                              void* d_out, int out_size) {
    const float* x     = (const float*)d_in[0];
    const float* h_in  = (const float*)d_in[1];
    const int*   nr    = (const int*)d_in[2];
    const int*   nc    = (const int*)d_in[3];
    const float* nv    = (const float*)d_in[4];
    const int*   er    = (const int*)d_in[5];
    const int*   ec    = (const int*)d_in[6];
    const float* ev    = (const float*)d_in[7];
    const float* W1    = (const float*)d_in[8];
    const float* b1    = (const float*)d_in[9];
    const float* gamma = (const float*)d_in[10];
    const float* beta  = (const float*)d_in[11];
    const float* W2    = (const float*)d_in[12];
    const float* b2    = (const float*)d_in[13];
    const float* Wi_n  = (const float*)d_in[14];
    const float* bi_n  = (const float*)d_in[15];
    const float* Wh_n  = (const float*)d_in[16];
    const float* bh_n  = (const float*)d_in[17];
    const float* Wi_e  = (const float*)d_in[18];
    const float* bi_e  = (const float*)d_in[19];
    const float* Wh_e  = (const float*)d_in[20];
    const float* bh_e  = (const float*)d_in[21];
    const float* w_on  = (const float*)d_in[22];
    const float* b_on  = (const float*)d_in[23];
    const float* w_oe  = (const float*)d_in[24];
    const float* b_oe  = (const float*)d_in[25];

    int Nx   = in_sizes[0] / NHID;
    int Nold = in_sizes[1] / NHID;
    int N    = Nx + Nold;
    int nnzN = in_sizes[2];
    int nnzE = in_sizes[5];
    float* out = (float*)d_out;

    // K6 needs >48KB dynamic shared
    static_assert(SM_FLOATS * 4 <= 101 * 1024, "smem");
    cudaFuncSetAttribute(k_gru, cudaFuncAttributeMaxDynamicSharedMemorySize,
                         SM_FLOATS * sizeof(float));

    k_zero<<<2048, 256>>>(N * (NHID / 4), N);

    {
        int tot = nnzN + nnzE;
        int blocks = (tot + 255) / 256;
        if (blocks > 65535 * 8) blocks = 65535 * 8;
        k_diag<<<blocks, 256>>>(nr, nc, nv, nnzN, er, ec, ev, nnzE);
    }

    {
        int n4 = Nold * (NHID / 4);
        k_copy_h<<<2048, 256>>>((const float4*)h_in, n4);
    }

    k_lin1<<<(Nx + 3) / 4, 256>>>(x, W1, b1, Nx);
    k_lin2<<<(Nx + 3) / 4, 256>>>(gamma, beta, W2, b2, Nx, Nold);

    {
        long long totW = (long long)(nnzN + nnzE) * 32;
        int blocks = (int)((totW + 255) / 256);
        k_spmm<<<blocks, 256>>>(nr, nc, nv, nnzN, er, ec, ev, nnzE);
    }

    k_gru<<<(N + 127) / 128, 128, SM_FLOATS * sizeof(float)>>>(
        Wi_n, bi_n, Wh_n, bh_n, Wi_e, bi_e, Wh_e, bh_e,
        w_on, b_on, w_oe, b_oe, N, out);
}

// round 2
// speedup vs baseline: 1.5126x; 1.5126x over previous
#include <cuda_runtime.h>
#include <math.h>

#define NHID 64
#define NMAX 400000
#define NXMAX 100000
#define BN_EPS 1e-5f

typedef unsigned long long u64;

// ---------------- scratch (device globals; no allocations) ----------------
__device__ __align__(256) float  g_dn[NMAX];
__device__ __align__(256) float  g_de[NMAX];
__device__ __align__(256) float  g_h [NMAX * NHID];
__device__ __align__(256) float  g_mn[NMAX * NHID];
__device__ __align__(256) float  g_me[NMAX * NHID];
__device__ __align__(256) float  g_t [NXMAX * NHID];
__device__ double g_sum[NHID];
__device__ double g_sumsq[NHID];

// ---------------- packed f32x2 helpers ----------------
__device__ __forceinline__ u64 pack2(float lo, float hi) {
    u64 r; asm("mov.b64 %0, {%1,%2};" : "=l"(r) : "f"(lo), "f"(hi)); return r;
}
__device__ __forceinline__ float2 unpack2(u64 v) {
    float2 r; asm("mov.b64 {%0,%1}, %2;" : "=f"(r.x), "=f"(r.y) : "l"(v)); return r;
}
__device__ __forceinline__ void fma2(u64& acc, u64 a, u64 b) {
    asm("fma.rn.f32x2 %0, %1, %2, %0;" : "+l"(acc) : "l"(a), "l"(b));
}
__device__ __forceinline__ float sigmf(float x) {
    return __fdividef(1.0f, 1.0f + __expf(-x));
}
__device__ __forceinline__ float tanhfast(float x) {
    return 2.0f * sigmf(2.0f * x) - 1.0f;
}

// ---------------- K0: zero scratch ----------------
__global__ void k_zero(int n4, int N) {
    int i = blockIdx.x * blockDim.x + threadIdx.x;
    int stride = gridDim.x * blockDim.x;
    float4 z = make_float4(0.f, 0.f, 0.f, 0.f);
    float4* mn4 = reinterpret_cast<float4*>(g_mn);
    float4* me4 = reinterpret_cast<float4*>(g_me);
    for (int j = i; j < n4; j += stride) { mn4[j] = z; me4[j] = z; }
    for (int j = i; j < N; j += stride) { g_dn[j] = 0.f; g_de[j] = 0.f; }
    if (i < NHID) { g_sum[i] = 0.0; g_sumsq[i] = 0.0; }
}

// ---------------- K1: diagonal extraction ----------------
__global__ void k_diag(const int* __restrict__ nr, const int* __restrict__ nc,
                       const float* __restrict__ nv, int nnzN,
                       const int* __restrict__ er, const int* __restrict__ ec,
                       const float* __restrict__ ev, int nnzE) {
    int i = blockIdx.x * blockDim.x + threadIdx.x;
    int stride = gridDim.x * blockDim.x;
    int tot = nnzN + nnzE;
    for (int j = i; j < tot; j += stride) {
        if (j < nnzN) {
            int r = nr[j], c = nc[j];
            if (r == c) atomicAdd(&g_dn[r], nv[j]);
        } else {
            int e = j - nnzN;
            int r = er[e], c = ec[e];
            if (r == c) atomicAdd(&g_de[r], ev[e]);
        }
    }
}

// ---------------- K2: copy h_in into g_h[0..Nold) ----------------
__global__ void k_copy_h(const float4* __restrict__ src, int n4) {
    int i = blockIdx.x * blockDim.x + threadIdx.x;
    int stride = gridDim.x * blockDim.x;
    float4* dst = reinterpret_cast<float4*>(g_h);
    for (int j = i; j < n4; j += stride) dst[j] = src[j];
}

// ---------------- K3: lin1 + BN stats (bank-conflict-free via pad 65) ----
// block = 256 threads = 4 rows x 64 outputs
__global__ void k_lin1(const float* __restrict__ x, const float* __restrict__ W1,
                       const float* __restrict__ b1, int Nx) {
    __shared__ float sW[NHID * 65];
    __shared__ float sX[4 * NHID];
    __shared__ float sP[NHID], sPq[NHID];
    int tid = threadIdx.x;
    for (int t = tid; t < NHID * NHID; t += blockDim.x)
        sW[(t >> 6) * 65 + (t & 63)] = W1[t];
    if (tid < NHID) { sP[tid] = 0.f; sPq[tid] = 0.f; }
    // stage 4 x-rows (coalesced float4)
    {
        int row0 = blockIdx.x * 4;
        if (tid < 64) {
            int rr = tid >> 4, cc = tid & 15;
            int row = row0 + rr;
            float4 v = make_float4(0.f, 0.f, 0.f, 0.f);
            if (row < Nx) v = reinterpret_cast<const float4*>(x + (size_t)row * NHID)[cc];
            reinterpret_cast<float4*>(sX + rr * NHID)[cc] = v;
        }
    }
    __syncthreads();
    int row = blockIdx.x * 4 + (tid >> 6);
    int j = tid & (NHID - 1);
    if (row < Nx) {
        const float* xr = sX + (tid >> 6) * NHID;
        float acc = b1[j];
        const float* wr = sW + j * 65;
#pragma unroll
        for (int k = 0; k < NHID; k++) acc += xr[k] * wr[k];
        g_t[(size_t)row * NHID + j] = acc;
        atomicAdd(&sP[j], acc);
        atomicAdd(&sPq[j], acc * acc);
    }
    __syncthreads();
    if (tid < NHID) {
        atomicAdd(&g_sum[tid], (double)sP[tid]);
        atomicAdd(&g_sumsq[tid], (double)sPq[tid]);
    }
}

// ---------------- K4: BN + ReLU + lin2 + h_update ----------------
__global__ void k_lin2(const float* __restrict__ gamma, const float* __restrict__ beta,
                       const float* __restrict__ W2, const float* __restrict__ b2,
                       int Nx, int Nold) {
    __shared__ float sW[NHID * 65];
    __shared__ float sT[4 * NHID];
    __shared__ float sScale[NHID], sShift[NHID];
    int tid = threadIdx.x;
    for (int t = tid; t < NHID * NHID; t += blockDim.x)
        sW[(t >> 6) * 65 + (t & 63)] = W2[t];
    if (tid < NHID) {
        double mu = g_sum[tid] / (double)Nx;
        double var = g_sumsq[tid] / (double)Nx - mu * mu;
        float inv = rsqrtf((float)var + BN_EPS);
        float sc = gamma[tid] * inv;
        sScale[tid] = sc;
        sShift[tid] = beta[tid] - (float)mu * sc;
    }
    __syncthreads();
    // stage 4 t-rows, apply BN+ReLU while staging
    {
        int row0 = blockIdx.x * 4;
        if (tid < 64) {
            int rr = tid >> 4, cc = tid & 15;
            int row = row0 + rr;
            float4 v = make_float4(0.f, 0.f, 0.f, 0.f);
            if (row < Nx) {
                v = reinterpret_cast<const float4*>(g_t + (size_t)row * NHID)[cc];
                int k0 = cc * 4;
                v.x = fmaxf(v.x * sScale[k0] + sShift[k0], 0.f);
                v.y = fmaxf(v.y * sScale[k0 + 1] + sShift[k0 + 1], 0.f);
                v.z = fmaxf(v.z * sScale[k0 + 2] + sShift[k0 + 2], 0.f);
                v.w = fmaxf(v.w * sScale[k0 + 3] + sShift[k0 + 3], 0.f);
            }
            reinterpret_cast<float4*>(sT + rr * NHID)[cc] = v;
        }
    }
    __syncthreads();
    int row = blockIdx.x * 4 + (tid >> 6);
    int j = tid & (NHID - 1);
    if (row < Nx) {
        const float* tr = sT + (tid >> 6) * NHID;
        float acc = b2[j];
        const float* wr = sW + j * 65;
#pragma unroll
        for (int k = 0; k < NHID; k++) acc += tr[k] * wr[k];
        acc *= g_dn[Nold + row];
        g_h[(size_t)(Nold + row) * NHID + j] = acc;
    }
}

// ---------------- K5: spmm (off-diagonal), 16 lanes per entry, v4 red ----
__global__ void k_spmm(const int* __restrict__ nr, const int* __restrict__ nc,
                       const float* __restrict__ nv, int nnzN,
                       const int* __restrict__ er, const int* __restrict__ ec,
                       const float* __restrict__ ev, int nnzE) {
    long long gtid = (long long)blockIdx.x * blockDim.x + threadIdx.x;
    long long e = gtid >> 4;
    int l = (int)(gtid & 15);
    long long tot = (long long)nnzN + nnzE;
    if (e >= tot) return;
    int r, c; float v; float* M;
    if (e < nnzN) {
        r = nr[e]; c = nc[e];
        if (r == c) return;
        v = nv[e]; M = g_mn;
    } else {
        long long q = e - nnzN;
        r = er[q]; c = ec[q];
        if (r == c) return;
        v = ev[q]; M = g_me;
    }
    float4 hv = reinterpret_cast<const float4*>(g_h + (size_t)c * NHID)[l];
    float* dst = M + (size_t)r * NHID + l * 4;
    asm volatile("red.global.add.v4.f32 [%0], {%1,%2,%3,%4};" ::
                 "l"(dst), "f"(hv.x * v), "f"(hv.y * v), "f"(hv.z * v), "f"(hv.w * v)
                 : "memory");
}

// ---------------- K6: fused dual-GRU + output heads (f32x2) ----------------
#define SM_WI 0
#define SM_WH (192 * 64)
#define SM_BI (2 * 192 * 64)
#define SM_BH (SM_BI + 192)
#define SM_WON (SM_BH + 192)
#define SM_WOE (SM_WON + 64)
#define SM_FLOATS (SM_WOE + 64)

__global__ void __launch_bounds__(128) k_gru(
    const float* __restrict__ Wi_n, const float* __restrict__ bi_n,
    const float* __restrict__ Wh_n, const float* __restrict__ bh_n,
    const float* __restrict__ Wi_e, const float* __restrict__ bi_e,
    const float* __restrict__ Wh_e, const float* __restrict__ bh_e,
    const float* __restrict__ w_on, const float* __restrict__ b_on,
    const float* __restrict__ w_oe, const float* __restrict__ b_oe,
    int N, float* __restrict__ out) {
    extern __shared__ float sm[];
    float* sWi = sm + SM_WI;
    float* sWh = sm + SM_WH;
    float* sBi = sm + SM_BI;
    float* sBh = sm + SM_BH;
    float* sWon = sm + SM_WON;
    float* sWoe = sm + SM_WOE;
    int tid = threadIdx.x;
    int i = blockIdx.x * blockDim.x + tid;
    bool active = i < N;

    u64 m2[32], h2[32];
    float hl[64];  // dynamic-indexed epilogue copy (local mem, coalesced LDL)
    float dn_i = 0.f, de_i = 0.f;
    if (active) {
        dn_i = g_dn[i];
        de_i = g_de[i];
        const float4* h4 = reinterpret_cast<const float4*>(g_h + (size_t)i * NHID);
        const ulonglong2* mm = reinterpret_cast<const ulonglong2*>(g_mn + (size_t)i * NHID);
#pragma unroll
        for (int k = 0; k < 16; k++) {
            float4 a = h4[k];
            hl[4 * k] = a.x; hl[4 * k + 1] = a.y; hl[4 * k + 2] = a.z; hl[4 * k + 3] = a.w;
            h2[2 * k] = pack2(a.x, a.y);
            h2[2 * k + 1] = pack2(a.z, a.w);
            ulonglong2 mv = mm[k];
            m2[2 * k] = mv.x; m2[2 * k + 1] = mv.y;
        }
    }
    float* out_h = out + 2 * (size_t)N;

    // ---- phase 1: node GRU ----
    for (int t = tid; t < 192 * 64; t += blockDim.x) { sWi[t] = Wi_n[t]; sWh[t] = Wh_n[t]; }
    for (int t = tid; t < 192; t += blockDim.x) { sBi[t] = bi_n[t]; sBh[t] = bh_n[t]; }
    if (tid < 64) { sWon[tid] = w_on[tid]; sWoe[tid] = w_oe[tid]; }
    __syncthreads();
    if (active) {
        for (int j = 0; j < NHID; j++) {
            u64 a_r = pack2(sBi[j], 0.f);
            u64 a_z = pack2(sBi[64 + j], 0.f);
            u64 a_n = pack2(sBi[128 + j], 0.f);
            u64 b_r = pack2(sBh[j], 0.f);
            u64 b_z = pack2(sBh[64 + j], 0.f);
            u64 b_n = pack2(sBh[128 + j], 0.f);
            const ulonglong2* w0 = reinterpret_cast<const ulonglong2*>(sWi + j * 64);
            const ulonglong2* w1 = reinterpret_cast<const ulonglong2*>(sWi + (64 + j) * 64);
            const ulonglong2* w2 = reinterpret_cast<const ulonglong2*>(sWi + (128 + j) * 64);
            const ulonglong2* v0 = reinterpret_cast<const ulonglong2*>(sWh + j * 64);
            const ulonglong2* v1 = reinterpret_cast<const ulonglong2*>(sWh + (64 + j) * 64);
            const ulonglong2* v2 = reinterpret_cast<const ulonglong2*>(sWh + (128 + j) * 64);
#pragma unroll
            for (int kk = 0; kk < 16; kk++) {
                ulonglong2 W0 = w0[kk], W1 = w1[kk], W2 = w2[kk];
                ulonglong2 V0 = v0[kk], V1 = v1[kk], V2 = v2[kk];
                u64 ma = m2[2 * kk], mb = m2[2 * kk + 1];
                u64 ha = h2[2 * kk], hb = h2[2 * kk + 1];
                fma2(a_r, ma, W0.x); fma2(a_r, mb, W0.y);
                fma2(a_z, ma, W1.x); fma2(a_z, mb, W1.y);
                fma2(a_n, ma, W2.x); fma2(a_n, mb, W2.y);
                fma2(b_r, ha, V0.x); fma2(b_r, hb, V0.y);
                fma2(b_z, ha, V1.x); fma2(b_z, hb, V1.y);
                fma2(b_n, ha, V2.x); fma2(b_n, hb, V2.y);
            }
            float2 pr = unpack2(a_r), pz = unpack2(a_z), pn = unpack2(a_n);
            float2 qr = unpack2(b_r), qz = unpack2(b_z), qn = unpack2(b_n);
            float r = sigmf(pr.x + pr.y + qr.x + qr.y);
            float z = sigmf(pz.x + pz.y + qz.x + qz.y);
            float ng = tanhfast(pn.x + pn.y + r * (qn.x + qn.y));
            float hv = (1.f - z) * ng + z * hl[j];
            out_h[(size_t)i * NHID + j] = dn_i * hv;  // partial
        }
    }
    __syncthreads();

    // ---- phase 2: edge GRU + combine + heads ----
    for (int t = tid; t < 192 * 64; t += blockDim.x) { sWi[t] = Wi_e[t]; sWh[t] = Wh_e[t]; }
    for (int t = tid; t < 192; t += blockDim.x) { sBi[t] = bi_e[t]; sBh[t] = bh_e[t]; }
    __syncthreads();
    if (active) {
        const ulonglong2* mm = reinterpret_cast<const ulonglong2*>(g_me + (size_t)i * NHID);
#pragma unroll
        for (int k = 0; k < 16; k++) {
            ulonglong2 mv = mm[k];
            m2[2 * k] = mv.x; m2[2 * k + 1] = mv.y;
        }
        float s_on = 0.f, s_oe = 0.f;
        for (int j = 0; j < NHID; j++) {
            u64 a_r = pack2(sBi[j], 0.f);
            u64 a_z = pack2(sBi[64 + j], 0.f);
            u64 a_n = pack2(sBi[128 + j], 0.f);
            u64 b_r = pack2(sBh[j], 0.f);
            u64 b_z = pack2(sBh[64 + j], 0.f);
            u64 b_n = pack2(sBh[128 + j], 0.f);
            const ulonglong2* w0 = reinterpret_cast<const ulonglong2*>(sWi + j * 64);
            const ulonglong2* w1 = reinterpret_cast<const ulonglong2*>(sWi + (64 + j) * 64);
            const ulonglong2* w2 = reinterpret_cast<const ulonglong2*>(sWi + (128 + j) * 64);
            const ulonglong2* v0 = reinterpret_cast<const ulonglong2*>(sWh + j * 64);
            const ulonglong2* v1 = reinterpret_cast<const ulonglong2*>(sWh + (64 + j) * 64);
            const ulonglong2* v2 = reinterpret_cast<const ulonglong2*>(sWh + (128 + j) * 64);
#pragma unroll
            for (int kk = 0; kk < 16; kk++) {
                ulonglong2 W0 = w0[kk], W1 = w1[kk], W2 = w2[kk];
                ulonglong2 V0 = v0[kk], V1 = v1[kk], V2 = v2[kk];
                u64 ma = m2[2 * kk], mb = m2[2 * kk + 1];
                u64 ha = h2[2 * kk], hb = h2[2 * kk + 1];
                fma2(a_r, ma, W0.x); fma2(a_r, mb, W0.y);
                fma2(a_z, ma, W1.x); fma2(a_z, mb, W1.y);
                fma2(a_n, ma, W2.x); fma2(a_n, mb, W2.y);
                fma2(b_r, ha, V0.x); fma2(b_r, hb, V0.y);
                fma2(b_z, ha, V1.x); fma2(b_z, hb, V1.y);
                fma2(b_n, ha, V2.x); fma2(b_n, hb, V2.y);
            }
            float2 pr = unpack2(a_r), pz = unpack2(a_z), pn = unpack2(a_n);
            float2 qr = unpack2(b_r), qz = unpack2(b_z), qn = unpack2(b_n);
            float r = sigmf(pr.x + pr.y + qr.x + qr.y);
            float z = sigmf(pz.x + pz.y + qz.x + qz.y);
            float ng = tanhfast(pn.x + pn.y + r * (qn.x + qn.y));
            float hv = (1.f - z) * ng + z * hl[j];
            size_t oi = (size_t)i * NHID + j;
            float hf = out_h[oi] + de_i * hv;
            out_h[oi] = hf;
            s_on += hf * sWon[j];
            s_oe += hf * sWoe[j];
        }
        float y = dn_i * (s_on + b_on[0]) + de_i * (s_oe + b_oe[0]);
        out[i] = sigmf(y);
        out[(size_t)N + i] = y;
    }
}

// ---------------- launch ----------------
extern "C" void kernel_launch(void* const* d_in, const int* in_sizes, int n_in,
                              void* d_out, int out_size) {
    const float* x     = (const float*)d_in[0];
    const float* h_in  = (const float*)d_in[1];
    const int*   nr    = (const int*)d_in[2];
    const int*   nc    = (const int*)d_in[3];
    const float* nv    = (const float*)d_in[4];
    const int*   er    = (const int*)d_in[5];
    const int*   ec    = (const int*)d_in[6];
    const float* ev    = (const float*)d_in[7];
    const float* W1    = (const float*)d_in[8];
    const float* b1    = (const float*)d_in[9];
    const float* gamma = (const float*)d_in[10];
    const float* beta  = (const float*)d_in[11];
    const float* W2    = (const float*)d_in[12];
    const float* b2    = (const float*)d_in[13];
    const float* Wi_n  = (const float*)d_in[14];
    const float* bi_n  = (const float*)d_in[15];
    const float* Wh_n  = (const float*)d_in[16];
    const float* bh_n  = (const float*)d_in[17];
    const float* Wi_e  = (const float*)d_in[18];
    const float* bi_e  = (const float*)d_in[19];
    const float* Wh_e  = (const float*)d_in[20];
    const float* bh_e  = (const float*)d_in[21];
    const float* w_on  = (const float*)d_in[22];
    const float* b_on  = (const float*)d_in[23];
    const float* w_oe  = (const float*)d_in[24];
    const float* b_oe  = (const float*)d_in[25];

    int Nx   = in_sizes[0] / NHID;
    int Nold = in_sizes[1] / NHID;
    int N    = Nx + Nold;
    int nnzN = in_sizes[2];
    int nnzE = in_sizes[5];
    float* out = (float*)d_out;

    static_assert(SM_FLOATS * 4 <= 101 * 1024, "smem");
    cudaFuncSetAttribute(k_gru, cudaFuncAttributeMaxDynamicSharedMemorySize,
                         SM_FLOATS * sizeof(float));

    k_zero<<<2048, 256>>>(N * (NHID / 4), N);

    {
        int tot = nnzN + nnzE;
        int blocks = (tot + 255) / 256;
        k_diag<<<blocks, 256>>>(nr, nc, nv, nnzN, er, ec, ev, nnzE);
    }

    {
        int n4 = Nold * (NHID / 4);
        k_copy_h<<<2048, 256>>>((const float4*)h_in, n4);
    }

    k_lin1<<<(Nx + 3) / 4, 256>>>(x, W1, b1, Nx);
    k_lin2<<<(Nx + 3) / 4, 256>>>(gamma, beta, W2, b2, Nx, Nold);

    {
        long long totW = ((long long)nnzN + nnzE) * 16;
        int blocks = (int)((totW + 255) / 256);
        k_spmm<<<blocks, 256>>>(nr, nc, nv, nnzN, er, ec, ev, nnzE);
    }

    k_gru<<<(N + 127) / 128, 128, SM_FLOATS * sizeof(float)>>>(
        Wi_n, bi_n, Wh_n, bh_n, Wi_e, bi_e, Wh_e, bh_e,
        w_on, b_on, w_oe, b_oe, N, out);
}

// round 4
// speedup vs baseline: 2.4567x; 1.6242x over previous
#include <cuda_runtime.h>
#include <math.h>

#define NHID 64
#define NMAX 400000
#define NXMAX 100000
#define NNZCAP 2200000
#define BN_EPS 1e-5f

typedef unsigned long long u64;

// ---------------- scratch (device globals; no allocations) ----------------
__device__ __align__(256) float  g_dn[NMAX];
__device__ __align__(256) float  g_de[NMAX];
__device__ __align__(256) float  g_h [NMAX * NHID];
__device__ __align__(256) float  g_mn[NMAX * NHID];
__device__ __align__(256) float  g_me[NMAX * NHID];
__device__ __align__(256) float  g_t [NXMAX * NHID];
__device__ double g_sum[NHID];
__device__ double g_sumsq[NHID];
// CSR build scratch
__device__ __align__(256) int   g_cnt_n[NMAX], g_cnt_e[NMAX];
__device__ __align__(256) int   g_cur_n[NMAX], g_cur_e[NMAX];
__device__ __align__(256) int   g_start_n[NMAX], g_start_e[NMAX];
__device__ __align__(256) int   g_coln[NNZCAP], g_cole[NNZCAP];
__device__ __align__(256) float g_valn[NNZCAP], g_vale[NNZCAP];
__device__ int g_bsum_n[4096], g_bsum_e[4096], g_boff_n[4096], g_boff_e[4096];
__device__ int g_dummy[4];

// ---------------- packed f32x2 helpers ----------------
__device__ __forceinline__ u64 pack2(float lo, float hi) {
    u64 r; asm("mov.b64 %0, {%1,%2};" : "=l"(r) : "f"(lo), "f"(hi)); return r;
}
__device__ __forceinline__ float2 unpack2(u64 v) {
    float2 r; asm("mov.b64 {%0,%1}, %2;" : "=f"(r.x), "=f"(r.y) : "l"(v)); return r;
}
__device__ __forceinline__ void fma2(u64& acc, u64 a, u64 b) {
    asm("fma.rn.f32x2 %0, %1, %2, %0;" : "+l"(acc) : "l"(a), "l"(b));
}
__device__ __forceinline__ float sigmf(float x) {
    return __fdividef(1.0f, 1.0f + __expf(-x));
}
__device__ __forceinline__ float tanhfast(float x) {
    return 2.0f * sigmf(2.0f * x) - 1.0f;
}

// ---------------- K0: zero small scratch ----------------
__global__ void k_zero_small(int N) {
    int i = blockIdx.x * blockDim.x + threadIdx.x;
    int stride = gridDim.x * blockDim.x;
    for (int j = i; j < N; j += stride) {
        g_dn[j] = 0.f; g_de[j] = 0.f;
        g_cnt_n[j] = 0; g_cnt_e[j] = 0;
        g_cur_n[j] = 0; g_cur_e[j] = 0;
    }
    if (i < NHID) { g_sum[i] = 0.0; g_sumsq[i] = 0.0; }
}

// ---------------- K1: histogram + diagonal extraction ----------------
__global__ void k_hist(const int* __restrict__ nr, const int* __restrict__ nc,
                       const float* __restrict__ nv, int nnzN,
                       const int* __restrict__ er, const int* __restrict__ ec,
                       const float* __restrict__ ev, int nnzE) {
    int i = blockIdx.x * blockDim.x + threadIdx.x;
    int stride = gridDim.x * blockDim.x;
    int tot = nnzN + nnzE;
    for (int j = i; j < tot; j += stride) {
        if (j < nnzN) {
            int r = nr[j], c = nc[j];
            if (r == c) atomicAdd(&g_dn[r], nv[j]);
            else atomicAdd(&g_cnt_n[r], 1);
        } else {
            int e = j - nnzN;
            int r = er[e], c = ec[e];
            if (r == c) atomicAdd(&g_de[r], ev[e]);
            else atomicAdd(&g_cnt_e[r], 1);
        }
    }
}

// ---------------- K2: copy h_in ----------------
__global__ void k_copy_h(const float4* __restrict__ src, int n4) {
    int i = blockIdx.x * blockDim.x + threadIdx.x;
    int stride = gridDim.x * blockDim.x;
    float4* dst = reinterpret_cast<float4*>(g_h);
    for (int j = i; j < n4; j += stride) dst[j] = src[j];
}

// ---------------- scans (template-selected arrays, no symbol lookups) ----
// PHASE 0: cnt -> start (block-local exclusive) + bsum
// PHASE 1: bsum -> boff (single block)
// PHASE 2: start += boff[blk]
template <int EDGE>
__global__ void k_scan1(int n) {
    const int* in = EDGE ? g_cnt_e : g_cnt_n;
    int* out = EDGE ? g_start_e : g_start_n;
    int* bsum = EDGE ? g_bsum_e : g_bsum_n;
    __shared__ int sh[256];
    int tid = threadIdx.x;
    int base = blockIdx.x * 4096 + tid * 16;
    int loc[16]; int s = 0;
#pragma unroll
    for (int k = 0; k < 16; k++) {
        loc[k] = (base + k < n) ? in[base + k] : 0;
        s += loc[k];
    }
    sh[tid] = s; __syncthreads();
    for (int off = 1; off < 256; off <<= 1) {
        int t2 = (tid >= off) ? sh[tid - off] : 0;
        __syncthreads();
        sh[tid] += t2;
        __syncthreads();
    }
    int incl = sh[tid];
    int run = incl - s;
#pragma unroll
    for (int k = 0; k < 16; k++) {
        if (base + k < n) out[base + k] = run;
        run += loc[k];
    }
    if (tid == 255) bsum[blockIdx.x] = incl;
}

template <int EDGE>
__global__ void k_scan2(int nblk) {
    const int* bsum = EDGE ? g_bsum_e : g_bsum_n;
    int* boff = EDGE ? g_boff_e : g_boff_n;
    __shared__ int sh[256];
    int tid = threadIdx.x;
    int base = tid * 16;
    int loc[16]; int s = 0;
#pragma unroll
    for (int k = 0; k < 16; k++) {
        loc[k] = (base + k < nblk) ? bsum[base + k] : 0;
        s += loc[k];
    }
    sh[tid] = s; __syncthreads();
    for (int off = 1; off < 256; off <<= 1) {
        int t2 = (tid >= off) ? sh[tid - off] : 0;
        __syncthreads();
        sh[tid] += t2;
        __syncthreads();
    }
    int incl = sh[tid];
    int run = incl - s;
#pragma unroll
    for (int k = 0; k < 16; k++) {
        if (base + k < nblk) boff[base + k] = run;
        run += loc[k];
    }
}

template <int EDGE>
__global__ void k_scan3(int n) {
    int* out = EDGE ? g_start_e : g_start_n;
    const int* boff = EDGE ? g_boff_e : g_boff_n;
    int i = blockIdx.x * blockDim.x + threadIdx.x;
    int stride = gridDim.x * blockDim.x;
    for (int j = i; j < n; j += stride) out[j] += boff[j >> 12];
}

// ---------------- K-scatter: build CSR col/val ----------------
__global__ void k_scatter(const int* __restrict__ nr, const int* __restrict__ nc,
                          const float* __restrict__ nv, int nnzN,
                          const int* __restrict__ er, const int* __restrict__ ec,
                          const float* __restrict__ ev, int nnzE) {
    int i = blockIdx.x * blockDim.x + threadIdx.x;
    int stride = gridDim.x * blockDim.x;
    int tot = nnzN + nnzE;
    for (int j = i; j < tot; j += stride) {
        if (j < nnzN) {
            int r = nr[j], c = nc[j];
            if (r != c) {
                int p = g_start_n[r] + atomicAdd(&g_cur_n[r], 1);
                g_coln[p] = c; g_valn[p] = nv[j];
            }
        } else {
            int e = j - nnzN;
            int r = er[e], c = ec[e];
            if (r != c) {
                int p = g_start_e[r] + atomicAdd(&g_cur_e[r], 1);
                g_cole[p] = c; g_vale[p] = ev[e];
            }
        }
    }
}

// ---------------- K-spmm CSR: warp per row, no atomics ----------------
__global__ void k_spmm_csr(int N) {
    int w = (blockIdx.x * blockDim.x + threadIdx.x) >> 5;
    int lane = threadIdx.x & 31;
    if (w >= 2 * N) return;
    bool node = w < N;
    int r = node ? w : w - N;
    const int* cols = node ? g_coln : g_cole;
    const float* vals = node ? g_valn : g_vale;
    int s = node ? g_start_n[r] : g_start_e[r];
    int cnt = node ? g_cnt_n[r] : g_cnt_e[r];
    float2 acc = make_float2(0.f, 0.f);
    for (int p = s; p < s + cnt; p++) {
        int c = cols[p];
        float v = vals[p];
        float2 hv = reinterpret_cast<const float2*>(g_h + (size_t)c * NHID)[lane];
        acc.x += v * hv.x;
        acc.y += v * hv.y;
    }
    float* M = node ? g_mn : g_me;
    reinterpret_cast<float2*>(M + (size_t)r * NHID)[lane] = acc;
}

// ---------------- K3: lin1 + BN stats (chunked, float4 pad-68) ----------
__global__ void k_lin1(const float* __restrict__ x, const float* __restrict__ W1,
                       const float* __restrict__ b1, int Nx) {
    __shared__ float sW[NHID * 68];
    __shared__ float sX[4 * NHID];
    __shared__ float sP[NHID], sPq[NHID];
    int tid = threadIdx.x;
    for (int t = tid; t < NHID * NHID; t += blockDim.x)
        sW[(t >> 6) * 68 + (t & 63)] = W1[t];
    if (tid < NHID) { sP[tid] = 0.f; sPq[tid] = 0.f; }
    int j = tid & 63, rsub = tid >> 6;
    float bj = b1[j];
    float psum = 0.f, psumq = 0.f;
    int nchunk = (Nx + 3) >> 2;
    for (int ch = blockIdx.x; ch < nchunk; ch += gridDim.x) {
        __syncthreads();
        if (tid < 64) {
            int rr = tid >> 4, cc = tid & 15;
            int row = ch * 4 + rr;
            float4 v = make_float4(0.f, 0.f, 0.f, 0.f);
            if (row < Nx) v = reinterpret_cast<const float4*>(x)[(size_t)row * 16 + cc];
            reinterpret_cast<float4*>(sX + rr * NHID)[cc] = v;
        }
        __syncthreads();
        int row = ch * 4 + rsub;
        if (row < Nx) {
            const float4* xr = reinterpret_cast<const float4*>(sX + rsub * NHID);
            const float4* wr = reinterpret_cast<const float4*>(sW + j * 68);
            float acc = bj;
#pragma unroll
            for (int k = 0; k < 16; k++) {
                float4 xv = xr[k], wv = wr[k];
                acc += xv.x * wv.x + xv.y * wv.y + xv.z * wv.z + xv.w * wv.w;
            }
            g_t[(size_t)row * NHID + j] = acc;
            psum += acc; psumq += acc * acc;
        }
    }
    atomicAdd(&sP[j], psum);
    atomicAdd(&sPq[j], psumq);
    __syncthreads();
    if (tid < NHID) {
        atomicAdd(&g_sum[tid], (double)sP[tid]);
        atomicAdd(&g_sumsq[tid], (double)sPq[tid]);
    }
}

// ---------------- K4: BN + ReLU + lin2 + h_update (chunked) ------------
__global__ void k_lin2(const float* __restrict__ gamma, const float* __restrict__ beta,
                       const float* __restrict__ W2, const float* __restrict__ b2,
                       int Nx, int Nold) {
    __shared__ float sW[NHID * 68];
    __shared__ float sT[4 * NHID];
    __shared__ float sScale[NHID], sShift[NHID];
    int tid = threadIdx.x;
    for (int t = tid; t < NHID * NHID; t += blockDim.x)
        sW[(t >> 6) * 68 + (t & 63)] = W2[t];
    if (tid < NHID) {
        double mu = g_sum[tid] / (double)Nx;
        double var = g_sumsq[tid] / (double)Nx - mu * mu;
        float inv = rsqrtf((float)var + BN_EPS);
        float sc = gamma[tid] * inv;
        sScale[tid] = sc;
        sShift[tid] = beta[tid] - (float)mu * sc;
    }
    int j = tid & 63, rsub = tid >> 6;
    float bj = b2[j];
    int nchunk = (Nx + 3) >> 2;
    for (int ch = blockIdx.x; ch < nchunk; ch += gridDim.x) {
        __syncthreads();
        if (tid < 64) {
            int rr = tid >> 4, cc = tid & 15;
            int row = ch * 4 + rr;
            float4 v = make_float4(0.f, 0.f, 0.f, 0.f);
            if (row < Nx) {
                v = reinterpret_cast<const float4*>(g_t)[(size_t)row * 16 + cc];
                int k0 = cc * 4;
                v.x = fmaxf(v.x * sScale[k0] + sShift[k0], 0.f);
                v.y = fmaxf(v.y * sScale[k0 + 1] + sShift[k0 + 1], 0.f);
                v.z = fmaxf(v.z * sScale[k0 + 2] + sShift[k0 + 2], 0.f);
                v.w = fmaxf(v.w * sScale[k0 + 3] + sShift[k0 + 3], 0.f);
            }
            reinterpret_cast<float4*>(sT + rr * NHID)[cc] = v;
        }
        __syncthreads();
        int row = ch * 4 + rsub;
        if (row < Nx) {
            const float4* tr = reinterpret_cast<const float4*>(sT + rsub * NHID);
            const float4* wr = reinterpret_cast<const float4*>(sW + j * 68);
            float acc = bj;
#pragma unroll
            for (int k = 0; k < 16; k++) {
                float4 tv = tr[k], wv = wr[k];
                acc += tv.x * wv.x + tv.y * wv.y + tv.z * wv.z + tv.w * wv.w;
            }
            acc *= g_dn[Nold + row];
            g_h[(size_t)(Nold + row) * NHID + j] = acc;
        }
    }
}

// ---------------- K6: single-phase dual-weight GRU + heads -------------
#define SMG_BIAS 49152
#define SMG_WON  (SMG_BIAS + 768)
#define SMG_WOE  (SMG_WON + 64)
#define SMG_TOT  (SMG_WOE + 64)

__global__ void __launch_bounds__(256) k_gru(
    const float* __restrict__ Wi_n, const float* __restrict__ bi_n,
    const float* __restrict__ Wh_n, const float* __restrict__ bh_n,
    const float* __restrict__ Wi_e, const float* __restrict__ bi_e,
    const float* __restrict__ Wh_e, const float* __restrict__ bh_e,
    const float* __restrict__ w_on, const float* __restrict__ b_on,
    const float* __restrict__ w_oe, const float* __restrict__ b_oe,
    int N, float* __restrict__ out) {
    extern __shared__ float sm[];
    int tid = threadIdx.x;
    {
        float4* s4 = reinterpret_cast<float4*>(sm);
        const float4* a0 = reinterpret_cast<const float4*>(Wi_n);
        const float4* a1 = reinterpret_cast<const float4*>(Wh_n);
        const float4* a2 = reinterpret_cast<const float4*>(Wi_e);
        const float4* a3 = reinterpret_cast<const float4*>(Wh_e);
        for (int t = tid; t < 3072; t += 256) {
            s4[t] = a0[t];
            s4[3072 + t] = a1[t];
            s4[6144 + t] = a2[t];
            s4[9216 + t] = a3[t];
        }
        if (tid < 192) {
            sm[SMG_BIAS + tid] = bi_n[tid];
            sm[SMG_BIAS + 192 + tid] = bh_n[tid];
            sm[SMG_BIAS + 384 + tid] = bi_e[tid];
            sm[SMG_BIAS + 576 + tid] = bh_e[tid];
        }
        if (tid < 64) {
            sm[SMG_WON + tid] = w_on[tid];
            sm[SMG_WOE + tid] = w_oe[tid];
        }
    }
    __syncthreads();

    int wid = tid >> 5, lane = tid & 31;
    bool isNode = wid < 4;
    int local = isNode ? 2 * (wid * 32 + lane) : 2 * ((wid - 4) * 32 + lane) + 1;
    int i = blockIdx.x * 256 + local;
    bool active = i < N;

    float dn_i = 0.f, de_i = 0.f;
    if (active) { dn_i = g_dn[i]; de_i = g_de[i]; }
    float scale  = isNode ? dn_i : de_i;
    float oscale = isNode ? de_i : dn_i;
    const float* mptr = isNode ? g_mn : g_me;
    const float* optr = isNode ? g_me : g_mn;
    const float* sWi = sm + (isNode ? 0 : 24576);
    const float* sWh = sWi + 12288;
    const float* sBi = sm + SMG_BIAS + (isNode ? 0 : 384);
    const float* sBh = sBi + 192;
    const float* oWi = sm + (isNode ? 24576 : 0);
    const float* oWh = oWi + 12288;
    const float* oBi = sm + SMG_BIAS + (isNode ? 384 : 0);
    const float* oBh = oBi + 192;
    const float* sWon = sm + SMG_WON;
    const float* sWoe = sm + SMG_WOE;

    u64 m2[32], h2[32];
    float hl[64];
    if (active) {
        const float4* h4 = reinterpret_cast<const float4*>(g_h + (size_t)i * NHID);
#pragma unroll
        for (int k = 0; k < 16; k++) {
            float4 a = h4[k];
            hl[4 * k] = a.x; hl[4 * k + 1] = a.y; hl[4 * k + 2] = a.z; hl[4 * k + 3] = a.w;
            h2[2 * k] = pack2(a.x, a.y);
            h2[2 * k + 1] = pack2(a.z, a.w);
        }
    }
    float* out_h = out + 2 * (size_t)N;
    float s_on = 0.f, s_oe = 0.f;

    bool did_main = active && (scale != 0.f);
    if (did_main) {
        const ulonglong2* mm = reinterpret_cast<const ulonglong2*>(mptr + (size_t)i * NHID);
#pragma unroll
        for (int k = 0; k < 16; k++) {
            ulonglong2 mv = mm[k];
            m2[2 * k] = mv.x; m2[2 * k + 1] = mv.y;
        }
        for (int j = 0; j < NHID; j++) {
            u64 a_r = pack2(sBi[j], 0.f);
            u64 a_z = pack2(sBi[64 + j], 0.f);
            u64 a_n = pack2(sBi[128 + j], 0.f);
            u64 b_r = pack2(sBh[j], 0.f);
            u64 b_z = pack2(sBh[64 + j], 0.f);
            u64 b_n = pack2(sBh[128 + j], 0.f);
            const ulonglong2* w0 = reinterpret_cast<const ulonglong2*>(sWi + j * 64);
            const ulonglong2* w1 = reinterpret_cast<const ulonglong2*>(sWi + (64 + j) * 64);
            const ulonglong2* w2 = reinterpret_cast<const ulonglong2*>(sWi + (128 + j) * 64);
            const ulonglong2* v0 = reinterpret_cast<const ulonglong2*>(sWh + j * 64);
            const ulonglong2* v1 = reinterpret_cast<const ulonglong2*>(sWh + (64 + j) * 64);
            const ulonglong2* v2 = reinterpret_cast<const ulonglong2*>(sWh + (128 + j) * 64);
#pragma unroll
            for (int kk = 0; kk < 16; kk++) {
                ulonglong2 W0 = w0[kk], W1 = w1[kk], W2 = w2[kk];
                ulonglong2 V0 = v0[kk], V1 = v1[kk], V2 = v2[kk];
                u64 ma = m2[2 * kk], mb = m2[2 * kk + 1];
                u64 ha = h2[2 * kk], hb = h2[2 * kk + 1];
                fma2(a_r, ma, W0.x); fma2(a_r, mb, W0.y);
                fma2(a_z, ma, W1.x); fma2(a_z, mb, W1.y);
                fma2(a_n, ma, W2.x); fma2(a_n, mb, W2.y);
                fma2(b_r, ha, V0.x); fma2(b_r, hb, V0.y);
                fma2(b_z, ha, V1.x); fma2(b_z, hb, V1.y);
                fma2(b_n, ha, V2.x); fma2(b_n, hb, V2.y);
            }
            float2 pr = unpack2(a_r), pz = unpack2(a_z), pn = unpack2(a_n);
            float2 qr = unpack2(b_r), qz = unpack2(b_z), qn = unpack2(b_n);
            float r = sigmf(pr.x + pr.y + qr.x + qr.y);
            float z = sigmf(pz.x + pz.y + qz.x + qz.y);
            float ng = tanhfast(pn.x + pn.y + r * (qn.x + qn.y));
            float hv = (1.f - z) * ng + z * hl[j];
            float hf = scale * hv;
            out_h[(size_t)i * NHID + j] = hf;
            s_on += hf * sWon[j];
            s_oe += hf * sWoe[j];
        }
    } else if (active) {
        float4 z4 = make_float4(0.f, 0.f, 0.f, 0.f);
        float4* o4 = reinterpret_cast<float4*>(out_h + (size_t)i * NHID);
#pragma unroll
        for (int k = 0; k < 16; k++) o4[k] = z4;
    }

    // rare general fallback: both dn and de nonzero on one row
    bool need2 = active && (oscale != 0.f);
    if (need2) {
        s_on = 0.f; s_oe = 0.f;
        const ulonglong2* mm = reinterpret_cast<const ulonglong2*>(optr + (size_t)i * NHID);
#pragma unroll
        for (int k = 0; k < 16; k++) {
            ulonglong2 mv = mm[k];
            m2[2 * k] = mv.x; m2[2 * k + 1] = mv.y;
        }
        for (int j = 0; j < NHID; j++) {
            u64 a_r = pack2(oBi[j], 0.f);
            u64 a_z = pack2(oBi[64 + j], 0.f);
            u64 a_n = pack2(oBi[128 + j], 0.f);
            u64 b_r = pack2(oBh[j], 0.f);
            u64 b_z = pack2(oBh[64 + j], 0.f);
            u64 b_n = pack2(oBh[128 + j], 0.f);
            const ulonglong2* w0 = reinterpret_cast<const ulonglong2*>(oWi + j * 64);
            const ulonglong2* w1 = reinterpret_cast<const ulonglong2*>(oWi + (64 + j) * 64);
            const ulonglong2* w2 = reinterpret_cast<const ulonglong2*>(oWi + (128 + j) * 64);
            const ulonglong2* v0 = reinterpret_cast<const ulonglong2*>(oWh + j * 64);
            const ulonglong2* v1 = reinterpret_cast<const ulonglong2*>(oWh + (64 + j) * 64);
            const ulonglong2* v2 = reinterpret_cast<const ulonglong2*>(oWh + (128 + j) * 64);
#pragma unroll
            for (int kk = 0; kk < 16; kk++) {
                ulonglong2 W0 = w0[kk], W1 = w1[kk], W2 = w2[kk];
                ulonglong2 V0 = v0[kk], V1 = v1[kk], V2 = v2[kk];
                u64 ma = m2[2 * kk], mb = m2[2 * kk + 1];
                u64 ha = h2[2 * kk], hb = h2[2 * kk + 1];
                fma2(a_r, ma, W0.x); fma2(a_r, mb, W0.y);
                fma2(a_z, ma, W1.x); fma2(a_z, mb, W1.y);
                fma2(a_n, ma, W2.x); fma2(a_n, mb, W2.y);
                fma2(b_r, ha, V0.x); fma2(b_r, hb, V0.y);
                fma2(b_z, ha, V1.x); fma2(b_z, hb, V1.y);
                fma2(b_n, ha, V2.x); fma2(b_n, hb, V2.y);
            }
            float2 pr = unpack2(a_r), pz = unpack2(a_z), pn = unpack2(a_n);
            float2 qr = unpack2(b_r), qz = unpack2(b_z), qn = unpack2(b_n);
            float r = sigmf(pr.x + pr.y + qr.x + qr.y);
            float z = sigmf(pz.x + pz.y + qz.x + qz.y);
            float ng = tanhfast(pn.x + pn.y + r * (qn.x + qn.y));
            float hv = (1.f - z) * ng + z * hl[j];
            size_t oi = (size_t)i * NHID + j;
            float hf = out_h[oi] + oscale * hv;
            out_h[oi] = hf;
            s_on += hf * sWon[j];
            s_oe += hf * sWoe[j];
        }
    }

    if (active) {
        float y = dn_i * (s_on + b_on[0]) + de_i * (s_oe + b_oe[0]);
        out[i] = sigmf(y);
        out[(size_t)N + i] = y;
    }
}

// ---------------- launch ----------------
extern "C" void kernel_launch(void* const* d_in, const int* in_sizes, int n_in,
                              void* d_out, int out_size) {
    const float* x     = (const float*)d_in[0];
    const float* h_in  = (const float*)d_in[1];
    const int*   nr    = (const int*)d_in[2];
    const int*   nc    = (const int*)d_in[3];
    const float* nv    = (const float*)d_in[4];
    const int*   er    = (const int*)d_in[5];
    const int*   ec    = (const int*)d_in[6];
    const float* ev    = (const float*)d_in[7];
    const float* W1    = (const float*)d_in[8];
    const float* b1    = (const float*)d_in[9];
    const float* gamma = (const float*)d_in[10];
    const float* beta  = (const float*)d_in[11];
    const float* W2    = (const float*)d_in[12];
    const float* b2    = (const float*)d_in[13];
    const float* Wi_n  = (const float*)d_in[14];
    const float* bi_n  = (const float*)d_in[15];
    const float* Wh_n  = (const float*)d_in[16];
    const float* bh_n  = (const float*)d_in[17];
    const float* Wi_e  = (const float*)d_in[18];
    const float* bi_e  = (const float*)d_in[19];
    const float* Wh_e  = (const float*)d_in[20];
    const float* bh_e  = (const float*)d_in[21];
    const float* w_on  = (const float*)d_in[22];
    const float* b_on  = (const float*)d_in[23];
    const float* w_oe  = (const float*)d_in[24];
    const float* b_oe  = (const float*)d_in[25];

    int Nx   = in_sizes[0] / NHID;
    int Nold = in_sizes[1] / NHID;
    int N    = Nx + Nold;
    int nnzN = in_sizes[2];
    int nnzE = in_sizes[5];
    float* out = (float*)d_out;

    cudaFuncSetAttribute(k_gru, cudaFuncAttributeMaxDynamicSharedMemorySize,
                         SMG_TOT * sizeof(float));

    k_zero_small<<<1024, 256>>>(N);
    k_hist<<<1024, 256>>>(nr, nc, nv, nnzN, er, ec, ev, nnzE);
    k_copy_h<<<2048, 256>>>((const float4*)h_in, Nold * (NHID / 4));

    k_lin1<<<512, 256>>>(x, W1, b1, Nx);
    k_lin2<<<512, 256>>>(gamma, beta, W2, b2, Nx, Nold);

    int nblk = (N + 4095) / 4096;
    k_scan1<0><<<nblk, 256>>>(N);
    k_scan2<0><<<1, 256>>>(nblk);
    k_scan3<0><<<256, 256>>>(N);
    k_scan1<1><<<nblk, 256>>>(N);
    k_scan2<1><<<1, 256>>>(nblk);
    k_scan3<1><<<256, 256>>>(N);

    k_scatter<<<1024, 256>>>(nr, nc, nv, nnzN, er, ec, ev, nnzE);

    {
        long long warps = 2LL * N;
        int blocks = (int)((warps * 32 + 255) / 256);
        k_spmm_csr<<<blocks, 256>>>(N);
    }

    k_gru<<<(N + 255) / 256, 256, SMG_TOT * sizeof(float)>>>(
        Wi_n, bi_n, Wh_n, bh_n, Wi_e, bi_e, Wh_e, bh_e,
        w_on, b_on, w_oe, b_oe, N, out);
}

// round 5
// speedup vs baseline: 2.5240x; 1.0274x over previous
#include <cuda_runtime.h>
#include <math.h>

#define NHID 64
#define NMAX 400000
#define NXMAX 100000
#define NNZCAP 2200000
#define BN_EPS 1e-5f

typedef unsigned long long u64;

// ---------------- scratch (device globals; no allocations) ----------------
__device__ __align__(256) float  g_dn[NMAX];
__device__ __align__(256) float  g_de[NMAX];
__device__ __align__(256) float  g_h [NMAX * NHID];
__device__ __align__(256) float  g_mn[NMAX * NHID];
__device__ __align__(256) float  g_me[NMAX * NHID];
__device__ __align__(256) float  g_t [NXMAX * NHID];
__device__ double g_sum[NHID];
__device__ double g_sumsq[NHID];
// CSR build scratch
__device__ __align__(256) int   g_cnt_n[NMAX], g_cnt_e[NMAX];
__device__ __align__(256) int   g_cur_n[NMAX], g_cur_e[NMAX];
__device__ __align__(256) int   g_start_n[NMAX], g_start_e[NMAX];
__device__ __align__(256) int2  g_pkn[NNZCAP], g_pke[NNZCAP];
__device__ int g_bsum_n[4096], g_bsum_e[4096], g_boff_n[4096], g_boff_e[4096];

// ---------------- packed f32x2 helpers ----------------
__device__ __forceinline__ u64 pack2(float lo, float hi) {
    u64 r; asm("mov.b64 %0, {%1,%2};" : "=l"(r) : "f"(lo), "f"(hi)); return r;
}
__device__ __forceinline__ float2 unpack2(u64 v) {
    float2 r; asm("mov.b64 {%0,%1}, %2;" : "=f"(r.x), "=f"(r.y) : "l"(v)); return r;
}
__device__ __forceinline__ void fma2(u64& acc, u64 a, u64 b) {
    asm("fma.rn.f32x2 %0, %1, %2, %0;" : "+l"(acc) : "l"(a), "l"(b));
}
__device__ __forceinline__ float sigmf(float x) {
    return __fdividef(1.0f, 1.0f + __expf(-x));
}
__device__ __forceinline__ float tanhfast(float x) {
    return 2.0f * sigmf(2.0f * x) - 1.0f;
}

// ---------------- K0: zero small scratch ----------------
__global__ void k_zero_small(int N) {
    int i = blockIdx.x * blockDim.x + threadIdx.x;
    int stride = gridDim.x * blockDim.x;
    for (int j = i; j < N; j += stride) {
        g_dn[j] = 0.f; g_de[j] = 0.f;
        g_cnt_n[j] = 0; g_cnt_e[j] = 0;
        g_cur_n[j] = 0; g_cur_e[j] = 0;
    }
    if (i < NHID) { g_sum[i] = 0.0; g_sumsq[i] = 0.0; }
}

// ---------------- K1: histogram + diagonal extraction ----------------
__global__ void k_hist(const int* __restrict__ nr, const int* __restrict__ nc,
                       const float* __restrict__ nv, int nnzN,
                       const int* __restrict__ er, const int* __restrict__ ec,
                       const float* __restrict__ ev, int nnzE) {
    int i = blockIdx.x * blockDim.x + threadIdx.x;
    int stride = gridDim.x * blockDim.x;
    int tot = nnzN + nnzE;
    for (int j = i; j < tot; j += stride) {
        if (j < nnzN) {
            int r = nr[j], c = nc[j];
            if (r == c) atomicAdd(&g_dn[r], nv[j]);
            else atomicAdd(&g_cnt_n[r], 1);
        } else {
            int e = j - nnzN;
            int r = er[e], c = ec[e];
            if (r == c) atomicAdd(&g_de[r], ev[e]);
            else atomicAdd(&g_cnt_e[r], 1);
        }
    }
}

// ---------------- K2: copy h_in ----------------
__global__ void k_copy_h(const float4* __restrict__ src, int n4) {
    int i = blockIdx.x * blockDim.x + threadIdx.x;
    int stride = gridDim.x * blockDim.x;
    float4* dst = reinterpret_cast<float4*>(g_h);
    for (int j = i; j < n4; j += stride) dst[j] = src[j];
}

// ---------------- scans ----------------
template <int EDGE>
__global__ void k_scan1(int n) {
    const int* in = EDGE ? g_cnt_e : g_cnt_n;
    int* out = EDGE ? g_start_e : g_start_n;
    int* bsum = EDGE ? g_bsum_e : g_bsum_n;
    __shared__ int sh[256];
    int tid = threadIdx.x;
    int base = blockIdx.x * 4096 + tid * 16;
    int loc[16]; int s = 0;
#pragma unroll
    for (int k = 0; k < 16; k++) {
        loc[k] = (base + k < n) ? in[base + k] : 0;
        s += loc[k];
    }
    sh[tid] = s; __syncthreads();
    for (int off = 1; off < 256; off <<= 1) {
        int t2 = (tid >= off) ? sh[tid - off] : 0;
        __syncthreads();
        sh[tid] += t2;
        __syncthreads();
    }
    int incl = sh[tid];
    int run = incl - s;
#pragma unroll
    for (int k = 0; k < 16; k++) {
        if (base + k < n) out[base + k] = run;
        run += loc[k];
    }
    if (tid == 255) bsum[blockIdx.x] = incl;
}

template <int EDGE>
__global__ void k_scan2(int nblk) {
    const int* bsum = EDGE ? g_bsum_e : g_bsum_n;
    int* boff = EDGE ? g_boff_e : g_boff_n;
    __shared__ int sh[256];
    int tid = threadIdx.x;
    int base = tid * 16;
    int loc[16]; int s = 0;
#pragma unroll
    for (int k = 0; k < 16; k++) {
        loc[k] = (base + k < nblk) ? bsum[base + k] : 0;
        s += loc[k];
    }
    sh[tid] = s; __syncthreads();
    for (int off = 1; off < 256; off <<= 1) {
        int t2 = (tid >= off) ? sh[tid - off] : 0;
        __syncthreads();
        sh[tid] += t2;
        __syncthreads();
    }
    int incl = sh[tid];
    int run = incl - s;
#pragma unroll
    for (int k = 0; k < 16; k++) {
        if (base + k < nblk) boff[base + k] = run;
        run += loc[k];
    }
}

template <int EDGE>
__global__ void k_scan3(int n) {
    int* out = EDGE ? g_start_e : g_start_n;
    const int* boff = EDGE ? g_boff_e : g_boff_n;
    int i = blockIdx.x * blockDim.x + threadIdx.x;
    int stride = gridDim.x * blockDim.x;
    for (int j = i; j < n; j += stride) out[j] += boff[j >> 12];
}

// ---------------- K-scatter: build packed CSR (col,val) ----------------
__global__ void k_scatter(const int* __restrict__ nr, const int* __restrict__ nc,
                          const float* __restrict__ nv, int nnzN,
                          const int* __restrict__ er, const int* __restrict__ ec,
                          const float* __restrict__ ev, int nnzE) {
    int i = blockIdx.x * blockDim.x + threadIdx.x;
    int stride = gridDim.x * blockDim.x;
    int tot = nnzN + nnzE;
    for (int j = i; j < tot; j += stride) {
        if (j < nnzN) {
            int r = nr[j], c = nc[j];
            if (r != c) {
                int p = g_start_n[r] + atomicAdd(&g_cur_n[r], 1);
                g_pkn[p] = make_int2(c, __float_as_int(nv[j]));
            }
        } else {
            int e = j - nnzN;
            int r = er[e], c = ec[e];
            if (r != c) {
                int p = g_start_e[r] + atomicAdd(&g_cur_e[r], 1);
                g_pke[p] = make_int2(c, __float_as_int(ev[e]));
            }
        }
    }
}

// ---------------- K-spmm CSR: warp per row, 4-deep pipeline ------------
__global__ void k_spmm_csr(int N) {
    int w = (blockIdx.x * blockDim.x + threadIdx.x) >> 5;
    int lane = threadIdx.x & 31;
    if (w >= 2 * N) return;
    bool node = w < N;
    int r = node ? w : w - N;
    const int2* pk = node ? g_pkn : g_pke;
    int s = node ? g_start_n[r] : g_start_e[r];
    int cnt = node ? g_cnt_n[r] : g_cnt_e[r];
    float2 acc = make_float2(0.f, 0.f);
    int p = s, e = s + cnt;
    for (; p + 4 <= e; p += 4) {
        int2 e0 = pk[p], e1 = pk[p + 1], e2 = pk[p + 2], e3 = pk[p + 3];
        float2 h0 = reinterpret_cast<const float2*>(g_h + (size_t)e0.x * NHID)[lane];
        float2 h1 = reinterpret_cast<const float2*>(g_h + (size_t)e1.x * NHID)[lane];
        float2 h2 = reinterpret_cast<const float2*>(g_h + (size_t)e2.x * NHID)[lane];
        float2 h3 = reinterpret_cast<const float2*>(g_h + (size_t)e3.x * NHID)[lane];
        float v0 = __int_as_float(e0.y), v1 = __int_as_float(e1.y);
        float v2 = __int_as_float(e2.y), v3 = __int_as_float(e3.y);
        acc.x += v0 * h0.x + v1 * h1.x + v2 * h2.x + v3 * h3.x;
        acc.y += v0 * h0.y + v1 * h1.y + v2 * h2.y + v3 * h3.y;
    }
    for (; p < e; p++) {
        int2 e0 = pk[p];
        float2 h0 = reinterpret_cast<const float2*>(g_h + (size_t)e0.x * NHID)[lane];
        float v0 = __int_as_float(e0.y);
        acc.x += v0 * h0.x;
        acc.y += v0 * h0.y;
    }
    float* M = node ? g_mn : g_me;
    reinterpret_cast<float2*>(M + (size_t)r * NHID)[lane] = acc;
}

// ---------------- K3: lin1, thread-per-row ----------------
__global__ void __launch_bounds__(256) k_lin1(
    const float* __restrict__ x, const float* __restrict__ W1,
    const float* __restrict__ b1, int Nx) {
    __shared__ float sW[4096];
    __shared__ float sB[64];
    int tid = threadIdx.x;
    for (int t = tid; t < 4096; t += 256) sW[t] = W1[t];
    if (tid < 64) sB[tid] = b1[tid];
    __syncthreads();
    int i = blockIdx.x * 256 + tid;
    if (i >= Nx) return;
    u64 x2[32];
    const ulonglong2* xr = reinterpret_cast<const ulonglong2*>(x + (size_t)i * NHID);
#pragma unroll
    for (int k = 0; k < 16; k++) { ulonglong2 v = xr[k]; x2[2 * k] = v.x; x2[2 * k + 1] = v.y; }
    float4* o = reinterpret_cast<float4*>(g_t + (size_t)i * NHID);
    for (int jg = 0; jg < 16; jg++) {
        float res[4];
#pragma unroll
        for (int jj = 0; jj < 4; jj++) {
            int j = jg * 4 + jj;
            u64 acc = pack2(sB[j], 0.f);
            const ulonglong2* wr = reinterpret_cast<const ulonglong2*>(sW + j * 64);
#pragma unroll
            for (int k = 0; k < 16; k++) {
                ulonglong2 wv = wr[k];
                fma2(acc, x2[2 * k], wv.x);
                fma2(acc, x2[2 * k + 1], wv.y);
            }
            float2 p = unpack2(acc);
            res[jj] = p.x + p.y;
        }
        o[jg] = make_float4(res[0], res[1], res[2], res[3]);
    }
}

// ---------------- K-stats: BN batch stats from g_t ----------------
__global__ void k_stats(int Nx) {
    __shared__ float sS[64], sQ[64];
    int tid = threadIdx.x;
    if (tid < 64) { sS[tid] = 0.f; sQ[tid] = 0.f; }
    __syncthreads();
    int cc = tid & 15;
    float4 s = make_float4(0.f, 0.f, 0.f, 0.f);
    float4 q = make_float4(0.f, 0.f, 0.f, 0.f);
    for (int r = blockIdx.x * 16 + (tid >> 4); r < Nx; r += gridDim.x * 16) {
        float4 v = reinterpret_cast<const float4*>(g_t)[(size_t)r * 16 + cc];
        s.x += v.x; s.y += v.y; s.z += v.z; s.w += v.w;
        q.x += v.x * v.x; q.y += v.y * v.y; q.z += v.z * v.z; q.w += v.w * v.w;
    }
    int c0 = cc * 4;
    atomicAdd(&sS[c0], s.x); atomicAdd(&sS[c0 + 1], s.y);
    atomicAdd(&sS[c0 + 2], s.z); atomicAdd(&sS[c0 + 3], s.w);
    atomicAdd(&sQ[c0], q.x); atomicAdd(&sQ[c0 + 1], q.y);
    atomicAdd(&sQ[c0 + 2], q.z); atomicAdd(&sQ[c0 + 3], q.w);
    __syncthreads();
    if (tid < 64) {
        atomicAdd(&g_sum[tid], (double)sS[tid]);
        atomicAdd(&g_sumsq[tid], (double)sQ[tid]);
    }
}

// ---------------- K4: BN + ReLU + lin2 + h_update, thread-per-row ------
__global__ void __launch_bounds__(256) k_lin2(
    const float* __restrict__ gamma, const float* __restrict__ beta,
    const float* __restrict__ W2, const float* __restrict__ b2,
    int Nx, int Nold) {
    __shared__ float sW[4096];
    __shared__ float sB[64];
    __shared__ float sScale[64], sShift[64];
    int tid = threadIdx.x;
    for (int t = tid; t < 4096; t += 256) sW[t] = W2[t];
    if (tid < 64) {
        sB[tid] = b2[tid];
        double mu = g_sum[tid] / (double)Nx;
        double var = g_sumsq[tid] / (double)Nx - mu * mu;
        float inv = rsqrtf((float)var + BN_EPS);
        float sc = gamma[tid] * inv;
        sScale[tid] = sc;
        sShift[tid] = beta[tid] - (float)mu * sc;
    }
    __syncthreads();
    int i = blockIdx.x * 256 + tid;
    if (i >= Nx) return;
    u64 x2[32];
    const float4* tr = reinterpret_cast<const float4*>(g_t + (size_t)i * NHID);
#pragma unroll
    for (int k = 0; k < 16; k++) {
        float4 v = tr[k];
        int k0 = k * 4;
        v.x = fmaxf(v.x * sScale[k0] + sShift[k0], 0.f);
        v.y = fmaxf(v.y * sScale[k0 + 1] + sShift[k0 + 1], 0.f);
        v.z = fmaxf(v.z * sScale[k0 + 2] + sShift[k0 + 2], 0.f);
        v.w = fmaxf(v.w * sScale[k0 + 3] + sShift[k0 + 3], 0.f);
        x2[2 * k] = pack2(v.x, v.y);
        x2[2 * k + 1] = pack2(v.z, v.w);
    }
    float dn = g_dn[Nold + i];
    float4* o = reinterpret_cast<float4*>(g_h + (size_t)(Nold + i) * NHID);
    for (int jg = 0; jg < 16; jg++) {
        float res[4];
#pragma unroll
        for (int jj = 0; jj < 4; jj++) {
            int j = jg * 4 + jj;
            u64 acc = pack2(sB[j], 0.f);
            const ulonglong2* wr = reinterpret_cast<const ulonglong2*>(sW + j * 64);
#pragma unroll
            for (int k = 0; k < 16; k++) {
                ulonglong2 wv = wr[k];
                fma2(acc, x2[2 * k], wv.x);
                fma2(acc, x2[2 * k + 1], wv.y);
            }
            float2 p = unpack2(acc);
            res[jj] = (p.x + p.y) * dn;
        }
        o[jg] = make_float4(res[0], res[1], res[2], res[3]);
    }
}

// ---------------- K6: single-phase dual-weight GRU + heads -------------
#define SMG_BIAS 49152
#define SMG_WON  (SMG_BIAS + 768)
#define SMG_WOE  (SMG_WON + 64)
#define SMG_TOT  (SMG_WOE + 64)

__global__ void __launch_bounds__(256) k_gru(
    const float* __restrict__ Wi_n, const float* __restrict__ bi_n,
    const float* __restrict__ Wh_n, const float* __restrict__ bh_n,
    const float* __restrict__ Wi_e, const float* __restrict__ bi_e,
    const float* __restrict__ Wh_e, const float* __restrict__ bh_e,
    const float* __restrict__ w_on, const float* __restrict__ b_on,
    const float* __restrict__ w_oe, const float* __restrict__ b_oe,
    int N, float* __restrict__ out) {
    extern __shared__ float sm[];
    int tid = threadIdx.x;
    {
        float4* s4 = reinterpret_cast<float4*>(sm);
        const float4* a0 = reinterpret_cast<const float4*>(Wi_n);
        const float4* a1 = reinterpret_cast<const float4*>(Wh_n);
        const float4* a2 = reinterpret_cast<const float4*>(Wi_e);
        const float4* a3 = reinterpret_cast<const float4*>(Wh_e);
        for (int t = tid; t < 3072; t += 256) {
            s4[t] = a0[t];
            s4[3072 + t] = a1[t];
            s4[6144 + t] = a2[t];
            s4[9216 + t] = a3[t];
        }
        if (tid < 192) {
            sm[SMG_BIAS + tid] = bi_n[tid];
            sm[SMG_BIAS + 192 + tid] = bh_n[tid];
            sm[SMG_BIAS + 384 + tid] = bi_e[tid];
            sm[SMG_BIAS + 576 + tid] = bh_e[tid];
        }
        if (tid < 64) {
            sm[SMG_WON + tid] = w_on[tid];
            sm[SMG_WOE + tid] = w_oe[tid];
        }
    }
    __syncthreads();

    int wid = tid >> 5, lane = tid & 31;
    bool isNode = wid < 4;
    int local = isNode ? 2 * (wid * 32 + lane) : 2 * ((wid - 4) * 32 + lane) + 1;
    int i = blockIdx.x * 256 + local;
    bool active = i < N;

    float dn_i = 0.f, de_i = 0.f;
    if (active) { dn_i = g_dn[i]; de_i = g_de[i]; }
    float scale  = isNode ? dn_i : de_i;
    float oscale = isNode ? de_i : dn_i;
    const float* mptr = isNode ? g_mn : g_me;
    const float* optr = isNode ? g_me : g_mn;
    const float* sWi = sm + (isNode ? 0 : 24576);
    const float* sWh = sWi + 12288;
    const float* sBi = sm + SMG_BIAS + (isNode ? 0 : 384);
    const float* sBh = sBi + 192;
    const float* oWi = sm + (isNode ? 24576 : 0);
    const float* oWh = oWi + 12288;
    const float* oBi = sm + SMG_BIAS + (isNode ? 384 : 0);
    const float* oBh = oBi + 192;
    const float* sWon = sm + SMG_WON;
    const float* sWoe = sm + SMG_WOE;

    u64 m2[32], h2[32];
    float hl[64];
    if (active) {
        const float4* h4 = reinterpret_cast<const float4*>(g_h + (size_t)i * NHID);
#pragma unroll
        for (int k = 0; k < 16; k++) {
            float4 a = h4[k];
            hl[4 * k] = a.x; hl[4 * k + 1] = a.y; hl[4 * k + 2] = a.z; hl[4 * k + 3] = a.w;
            h2[2 * k] = pack2(a.x, a.y);
            h2[2 * k + 1] = pack2(a.z, a.w);
        }
    }
    float* out_h = out + 2 * (size_t)N;
    float s_on = 0.f, s_oe = 0.f;

    bool did_main = active && (scale != 0.f);
    if (did_main) {
        const ulonglong2* mm = reinterpret_cast<const ulonglong2*>(mptr + (size_t)i * NHID);
#pragma unroll
        for (int k = 0; k < 16; k++) {
            ulonglong2 mv = mm[k];
            m2[2 * k] = mv.x; m2[2 * k + 1] = mv.y;
        }
        for (int j = 0; j < NHID; j++) {
            u64 a_r = pack2(sBi[j], 0.f);
            u64 a_z = pack2(sBi[64 + j], 0.f);
            u64 a_n = pack2(sBi[128 + j], 0.f);
            u64 b_r = pack2(sBh[j], 0.f);
            u64 b_z = pack2(sBh[64 + j], 0.f);
            u64 b_n = pack2(sBh[128 + j], 0.f);
            const ulonglong2* w0 = reinterpret_cast<const ulonglong2*>(sWi + j * 64);
            const ulonglong2* w1 = reinterpret_cast<const ulonglong2*>(sWi + (64 + j) * 64);
            const ulonglong2* w2 = reinterpret_cast<const ulonglong2*>(sWi + (128 + j) * 64);
            const ulonglong2* v0 = reinterpret_cast<const ulonglong2*>(sWh + j * 64);
            const ulonglong2* v1 = reinterpret_cast<const ulonglong2*>(sWh + (64 + j) * 64);
            const ulonglong2* v2 = reinterpret_cast<const ulonglong2*>(sWh + (128 + j) * 64);
#pragma unroll
            for (int kk = 0; kk < 16; kk++) {
                ulonglong2 W0 = w0[kk], W1 = w1[kk], W2 = w2[kk];
                ulonglong2 V0 = v0[kk], V1 = v1[kk], V2 = v2[kk];
                u64 ma = m2[2 * kk], mb = m2[2 * kk + 1];
                u64 ha = h2[2 * kk], hb = h2[2 * kk + 1];
                fma2(a_r, ma, W0.x); fma2(a_r, mb, W0.y);
                fma2(a_z, ma, W1.x); fma2(a_z, mb, W1.y);
                fma2(a_n, ma, W2.x); fma2(a_n, mb, W2.y);
                fma2(b_r, ha, V0.x); fma2(b_r, hb, V0.y);
                fma2(b_z, ha, V1.x); fma2(b_z, hb, V1.y);
                fma2(b_n, ha, V2.x); fma2(b_n, hb, V2.y);
            }
            float2 pr = unpack2(a_r), pz = unpack2(a_z), pn = unpack2(a_n);
            float2 qr = unpack2(b_r), qz = unpack2(b_z), qn = unpack2(b_n);
            float r = sigmf(pr.x + pr.y + qr.x + qr.y);
            float z = sigmf(pz.x + pz.y + qz.x + qz.y);
            float ng = tanhfast(pn.x + pn.y + r * (qn.x + qn.y));
            float hv = (1.f - z) * ng + z * hl[j];
            float hf = scale * hv;
            out_h[(size_t)i * NHID + j] = hf;
            s_on += hf * sWon[j];
            s_oe += hf * sWoe[j];
        }
    } else if (active) {
        float4 z4 = make_float4(0.f, 0.f, 0.f, 0.f);
        float4* o4 = reinterpret_cast<float4*>(out_h + (size_t)i * NHID);
#pragma unroll
        for (int k = 0; k < 16; k++) o4[k] = z4;
    }

    bool need2 = active && (oscale != 0.f);
    if (need2) {
        s_on = 0.f; s_oe = 0.f;
        const ulonglong2* mm = reinterpret_cast<const ulonglong2*>(optr + (size_t)i * NHID);
#pragma unroll
        for (int k = 0; k < 16; k++) {
            ulonglong2 mv = mm[k];
            m2[2 * k] = mv.x; m2[2 * k + 1] = mv.y;
        }
        for (int j = 0; j < NHID; j++) {
            u64 a_r = pack2(oBi[j], 0.f);
            u64 a_z = pack2(oBi[64 + j], 0.f);
            u64 a_n = pack2(oBi[128 + j], 0.f);
            u64 b_r = pack2(oBh[j], 0.f);
            u64 b_z = pack2(oBh[64 + j], 0.f);
            u64 b_n = pack2(oBh[128 + j], 0.f);
            const ulonglong2* w0 = reinterpret_cast<const ulonglong2*>(oWi + j * 64);
            const ulonglong2* w1 = reinterpret_cast<const ulonglong2*>(oWi + (64 + j) * 64);
            const ulonglong2* w2 = reinterpret_cast<const ulonglong2*>(oWi + (128 + j) * 64);
            const ulonglong2* v0 = reinterpret_cast<const ulonglong2*>(oWh + j * 64);
            const ulonglong2* v1 = reinterpret_cast<const ulonglong2*>(oWh + (64 + j) * 64);
            const ulonglong2* v2 = reinterpret_cast<const ulonglong2*>(oWh + (128 + j) * 64);
#pragma unroll
            for (int kk = 0; kk < 16; kk++) {
                ulonglong2 W0 = w0[kk], W1 = w1[kk], W2 = w2[kk];
                ulonglong2 V0 = v0[kk], V1 = v1[kk], V2 = v2[kk];
                u64 ma = m2[2 * kk], mb = m2[2 * kk + 1];
                u64 ha = h2[2 * kk], hb = h2[2 * kk + 1];
                fma2(a_r, ma, W0.x); fma2(a_r, mb, W0.y);
                fma2(a_z, ma, W1.x); fma2(a_z, mb, W1.y);
                fma2(a_n, ma, W2.x); fma2(a_n, mb, W2.y);
                fma2(b_r, ha, V0.x); fma2(b_r, hb, V0.y);
                fma2(b_z, ha, V1.x); fma2(b_z, hb, V1.y);
                fma2(b_n, ha, V2.x); fma2(b_n, hb, V2.y);
            }
            float2 pr = unpack2(a_r), pz = unpack2(a_z), pn = unpack2(a_n);
            float2 qr = unpack2(b_r), qz = unpack2(b_z), qn = unpack2(b_n);
            float r = sigmf(pr.x + pr.y + qr.x + qr.y);
            float z = sigmf(pz.x + pz.y + qz.x + qz.y);
            float ng = tanhfast(pn.x + pn.y + r * (qn.x + qn.y));
            float hv = (1.f - z) * ng + z * hl[j];
            size_t oi = (size_t)i * NHID + j;
            float hf = out_h[oi] + oscale * hv;
            out_h[oi] = hf;
            s_on += hf * sWon[j];
            s_oe += hf * sWoe[j];
        }
    }

    if (active) {
        float y = dn_i * (s_on + b_on[0]) + de_i * (s_oe + b_oe[0]);
        out[i] = sigmf(y);
        out[(size_t)N + i] = y;
    }
}

// ---------------- launch ----------------
extern "C" void kernel_launch(void* const* d_in, const int* in_sizes, int n_in,
                              void* d_out, int out_size) {
    const float* x     = (const float*)d_in[0];
    const float* h_in  = (const float*)d_in[1];
    const int*   nr    = (const int*)d_in[2];
    const int*   nc    = (const int*)d_in[3];
    const float* nv    = (const float*)d_in[4];
    const int*   er    = (const int*)d_in[5];
    const int*   ec    = (const int*)d_in[6];
    const float* ev    = (const float*)d_in[7];
    const float* W1    = (const float*)d_in[8];
    const float* b1    = (const float*)d_in[9];
    const float* gamma = (const float*)d_in[10];
    const float* beta  = (const float*)d_in[11];
    const float* W2    = (const float*)d_in[12];
    const float* b2    = (const float*)d_in[13];
    const float* Wi_n  = (const float*)d_in[14];
    const float* bi_n  = (const float*)d_in[15];
    const float* Wh_n  = (const float*)d_in[16];
    const float* bh_n  = (const float*)d_in[17];
    const float* Wi_e  = (const float*)d_in[18];
    const float* bi_e  = (const float*)d_in[19];
    const float* Wh_e  = (const float*)d_in[20];
    const float* bh_e  = (const float*)d_in[21];
    const float* w_on  = (const float*)d_in[22];
    const float* b_on  = (const float*)d_in[23];
    const float* w_oe  = (const float*)d_in[24];
    const float* b_oe  = (const float*)d_in[25];

    int Nx   = in_sizes[0] / NHID;
    int Nold = in_sizes[1] / NHID;
    int N    = Nx + Nold;
    int nnzN = in_sizes[2];
    int nnzE = in_sizes[5];
    float* out = (float*)d_out;

    cudaFuncSetAttribute(k_gru, cudaFuncAttributeMaxDynamicSharedMemorySize,
                         SMG_TOT * sizeof(float));

    k_zero_small<<<1024, 256>>>(N);
    k_hist<<<1024, 256>>>(nr, nc, nv, nnzN, er, ec, ev, nnzE);
    k_copy_h<<<2048, 256>>>((const float4*)h_in, Nold * (NHID / 4));

    k_lin1<<<(Nx + 255) / 256, 256>>>(x, W1, b1, Nx);
    k_stats<<<256, 256>>>(Nx);
    k_lin2<<<(Nx + 255) / 256, 256>>>(gamma, beta, W2, b2, Nx, Nold);

    int nblk = (N + 4095) / 4096;
    k_scan1<0><<<nblk, 256>>>(N);
    k_scan2<0><<<1, 256>>>(nblk);
    k_scan3<0><<<256, 256>>>(N);
    k_scan1<1><<<nblk, 256>>>(N);
    k_scan2<1><<<1, 256>>>(nblk);
    k_scan3<1><<<256, 256>>>(N);

    k_scatter<<<1024, 256>>>(nr, nc, nv, nnzN, er, ec, ev, nnzE);

    {
        long long warps = 2LL * N;
        int blocks = (int)((warps * 32 + 255) / 256);
        k_spmm_csr<<<blocks, 256>>>(N);
    }

    k_gru<<<(N + 255) / 256, 256, SMG_TOT * sizeof(float)>>>(
        Wi_n, bi_n, Wh_n, bh_n, Wi_e, bi_e, Wh_e, bh_e,
        w_on, b_on, w_oe, b_oe, N, out);
}

// round 6
// speedup vs baseline: 3.3009x; 1.3078x over previous
#include <cuda_runtime.h>
#include <math.h>

#define NHID 64
#define NMAX 400000
#define NXMAX 100000
#define NNZCAP 2200000
#define BN_EPS 1e-5f
#define NSM 148

typedef unsigned long long u64;

// ---------------- scratch (device globals; no allocations) ----------------
__device__ __align__(256) float  g_dn[NMAX];
__device__ __align__(256) float  g_de[NMAX];
__device__ __align__(256) float  g_h [NMAX * NHID];
__device__ __align__(256) float  g_mn[NMAX * NHID];
__device__ __align__(256) float  g_me[NMAX * NHID];
__device__ __align__(256) float  g_t [NXMAX * NHID];
__device__ double g_sum[NHID];
__device__ double g_sumsq[NHID];
// CSR build scratch
__device__ __align__(256) int   g_cnt_n[NMAX], g_cnt_e[NMAX];
__device__ __align__(256) int   g_cur_n[NMAX], g_cur_e[NMAX];
__device__ __align__(256) int   g_start_n[NMAX], g_start_e[NMAX];
__device__ __align__(256) int2  g_pkn[NNZCAP], g_pke[NNZCAP];
__device__ int g_bsum_n[4096], g_bsum_e[4096], g_boff_n[4096], g_boff_e[4096];

// ---------------- packed f32x2 helpers ----------------
__device__ __forceinline__ u64 pack2(float lo, float hi) {
    u64 r; asm("mov.b64 %0, {%1,%2};" : "=l"(r) : "f"(lo), "f"(hi)); return r;
}
__device__ __forceinline__ float2 unpack2(u64 v) {
    float2 r; asm("mov.b64 {%0,%1}, %2;" : "=f"(r.x), "=f"(r.y) : "l"(v)); return r;
}
__device__ __forceinline__ void fma2(u64& acc, u64 a, u64 b) {
    asm("fma.rn.f32x2 %0, %1, %2, %0;" : "+l"(acc) : "l"(a), "l"(b));
}
__device__ __forceinline__ float sigmf(float x) {
    return __fdividef(1.0f, 1.0f + __expf(-x));
}
__device__ __forceinline__ float tanhfast(float x) {
    return 2.0f * sigmf(2.0f * x) - 1.0f;
}

// ---------------- K0: zero scratch + copy h_in (merged) ----------------
__global__ void k_init(const float4* __restrict__ h_src, int n4, int N) {
    int i = blockIdx.x * blockDim.x + threadIdx.x;
    int stride = gridDim.x * blockDim.x;
    float4* dst = reinterpret_cast<float4*>(g_h);
    for (int j = i; j < n4; j += stride) dst[j] = h_src[j];
    for (int j = i; j < N; j += stride) {
        g_dn[j] = 0.f; g_de[j] = 0.f;
        g_cnt_n[j] = 0; g_cnt_e[j] = 0;
        g_cur_n[j] = 0; g_cur_e[j] = 0;
    }
    if (i < NHID) { g_sum[i] = 0.0; g_sumsq[i] = 0.0; }
}

// ---------------- K1: histogram + diagonal extraction ----------------
__global__ void k_hist(const int* __restrict__ nr, const int* __restrict__ nc,
                       const float* __restrict__ nv, int nnzN,
                       const int* __restrict__ er, const int* __restrict__ ec,
                       const float* __restrict__ ev, int nnzE) {
    int i = blockIdx.x * blockDim.x + threadIdx.x;
    int stride = gridDim.x * blockDim.x;
    int tot = nnzN + nnzE;
    for (int j = i; j < tot; j += stride) {
        if (j < nnzN) {
            int r = nr[j], c = nc[j];
            if (r == c) atomicAdd(&g_dn[r], nv[j]);
            else atomicAdd(&g_cnt_n[r], 1);
        } else {
            int e = j - nnzN;
            int r = er[e], c = ec[e];
            if (r == c) atomicAdd(&g_de[r], ev[e]);
            else atomicAdd(&g_cnt_e[r], 1);
        }
    }
}

// ---------------- scans (blockIdx.y: 0=node, 1=edge) ----------------
__global__ void k_scan1(int n) {
    int edge = blockIdx.y;
    const int* in = edge ? g_cnt_e : g_cnt_n;
    int* out = edge ? g_start_e : g_start_n;
    int* bsum = edge ? g_bsum_e : g_bsum_n;
    __shared__ int sh[256];
    int tid = threadIdx.x;
    int base = blockIdx.x * 4096 + tid * 16;
    int loc[16]; int s = 0;
#pragma unroll
    for (int k = 0; k < 16; k++) {
        loc[k] = (base + k < n) ? in[base + k] : 0;
        s += loc[k];
    }
    sh[tid] = s; __syncthreads();
    for (int off = 1; off < 256; off <<= 1) {
        int t2 = (tid >= off) ? sh[tid - off] : 0;
        __syncthreads();
        sh[tid] += t2;
        __syncthreads();
    }
    int incl = sh[tid];
    int run = incl - s;
#pragma unroll
    for (int k = 0; k < 16; k++) {
        if (base + k < n) out[base + k] = run;
        run += loc[k];
    }
    if (tid == 255) bsum[blockIdx.x] = incl;
}

__global__ void k_scan2(int nblk) {
    int edge = blockIdx.x;
    const int* bsum = edge ? g_bsum_e : g_bsum_n;
    int* boff = edge ? g_boff_e : g_boff_n;
    __shared__ int sh[256];
    int tid = threadIdx.x;
    int base = tid * 16;
    int loc[16]; int s = 0;
#pragma unroll
    for (int k = 0; k < 16; k++) {
        loc[k] = (base + k < nblk) ? bsum[base + k] : 0;
        s += loc[k];
    }
    sh[tid] = s; __syncthreads();
    for (int off = 1; off < 256; off <<= 1) {
        int t2 = (tid >= off) ? sh[tid - off] : 0;
        __syncthreads();
        sh[tid] += t2;
        __syncthreads();
    }
    int incl = sh[tid];
    int run = incl - s;
#pragma unroll
    for (int k = 0; k < 16; k++) {
        if (base + k < nblk) boff[base + k] = run;
        run += loc[k];
    }
}

__global__ void k_scan3(int n) {
    int edge = blockIdx.y;
    int* out = edge ? g_start_e : g_start_n;
    const int* boff = edge ? g_boff_e : g_boff_n;
    int i = blockIdx.x * blockDim.x + threadIdx.x;
    int stride = gridDim.x * blockDim.x;
    for (int j = i; j < n; j += stride) out[j] += boff[j >> 12];
}

// ---------------- K-scatter: build packed CSR, FILTERED by dn/de -------
// Only scatter entries whose destination row will actually be consumed:
// m_n[r] is read by k_gru iff dn[r] != 0; m_e[r] iff de[r] != 0.
__global__ void k_scatter(const int* __restrict__ nr, const int* __restrict__ nc,
                          const float* __restrict__ nv, int nnzN,
                          const int* __restrict__ er, const int* __restrict__ ec,
                          const float* __restrict__ ev, int nnzE) {
    int i = blockIdx.x * blockDim.x + threadIdx.x;
    int stride = gridDim.x * blockDim.x;
    int tot = nnzN + nnzE;
    for (int j = i; j < tot; j += stride) {
        if (j < nnzN) {
            int r = nr[j], c = nc[j];
            if (r != c && g_dn[r] != 0.f) {
                int p = g_start_n[r] + atomicAdd(&g_cur_n[r], 1);
                g_pkn[p] = make_int2(c, __float_as_int(nv[j]));
            }
        } else {
            int e = j - nnzN;
            int r = er[e], c = ec[e];
            if (r != c && g_de[r] != 0.f) {
                int p = g_start_e[r] + atomicAdd(&g_cur_e[r], 1);
                g_pke[p] = make_int2(c, __float_as_int(ev[e]));
            }
        }
    }
}

// ---------------- K-spmm CSR: warp per row, filtered, count = g_cur ----
__global__ void k_spmm_csr(int N) {
    int w = (blockIdx.x * blockDim.x + threadIdx.x) >> 5;
    int lane = threadIdx.x & 31;
    if (w >= 2 * N) return;
    bool node = w < N;
    int r = node ? w : w - N;
    float scale = node ? g_dn[r] : g_de[r];
    if (scale == 0.f) return;   // row never consumed: skip gather AND write
    const int2* pk = node ? g_pkn : g_pke;
    int s = node ? g_start_n[r] : g_start_e[r];
    int cnt = node ? g_cur_n[r] : g_cur_e[r];  // entries actually scattered
    float2 acc = make_float2(0.f, 0.f);
    int p = s, e = s + cnt;
    for (; p + 4 <= e; p += 4) {
        int2 e0 = pk[p], e1 = pk[p + 1], e2 = pk[p + 2], e3 = pk[p + 3];
        float2 h0 = reinterpret_cast<const float2*>(g_h + (size_t)e0.x * NHID)[lane];
        float2 h1 = reinterpret_cast<const float2*>(g_h + (size_t)e1.x * NHID)[lane];
        float2 h2 = reinterpret_cast<const float2*>(g_h + (size_t)e2.x * NHID)[lane];
        float2 h3 = reinterpret_cast<const float2*>(g_h + (size_t)e3.x * NHID)[lane];
        float v0 = __int_as_float(e0.y), v1 = __int_as_float(e1.y);
        float v2 = __int_as_float(e2.y), v3 = __int_as_float(e3.y);
        acc.x += v0 * h0.x + v1 * h1.x + v2 * h2.x + v3 * h3.x;
        acc.y += v0 * h0.y + v1 * h1.y + v2 * h2.y + v3 * h3.y;
    }
    for (; p < e; p++) {
        int2 e0 = pk[p];
        float2 h0 = reinterpret_cast<const float2*>(g_h + (size_t)e0.x * NHID)[lane];
        float v0 = __int_as_float(e0.y);
        acc.x += v0 * h0.x;
        acc.y += v0 * h0.y;
    }
    float* M = node ? g_mn : g_me;
    reinterpret_cast<float2*>(M + (size_t)r * NHID)[lane] = acc;
}

// ---------------- K3: lin1, thread-per-row ----------------
__global__ void __launch_bounds__(256) k_lin1(
    const float* __restrict__ x, const float* __restrict__ W1,
    const float* __restrict__ b1, int Nx) {
    __shared__ float sW[4096];
    __shared__ float sB[64];
    int tid = threadIdx.x;
    for (int t = tid; t < 4096; t += 256) sW[t] = W1[t];
    if (tid < 64) sB[tid] = b1[tid];
    __syncthreads();
    int i = blockIdx.x * 256 + tid;
    if (i >= Nx) return;
    u64 x2[32];
    const ulonglong2* xr = reinterpret_cast<const ulonglong2*>(x + (size_t)i * NHID);
#pragma unroll
    for (int k = 0; k < 16; k++) { ulonglong2 v = xr[k]; x2[2 * k] = v.x; x2[2 * k + 1] = v.y; }
    float4* o = reinterpret_cast<float4*>(g_t + (size_t)i * NHID);
    for (int jg = 0; jg < 16; jg++) {
        float res[4];
#pragma unroll
        for (int jj = 0; jj < 4; jj++) {
            int j = jg * 4 + jj;
            u64 acc = pack2(sB[j], 0.f);
            const ulonglong2* wr = reinterpret_cast<const ulonglong2*>(sW + j * 64);
#pragma unroll
            for (int k = 0; k < 16; k++) {
                ulonglong2 wv = wr[k];
                fma2(acc, x2[2 * k], wv.x);
                fma2(acc, x2[2 * k + 1], wv.y);
            }
            float2 p = unpack2(acc);
            res[jj] = p.x + p.y;
        }
        o[jg] = make_float4(res[0], res[1], res[2], res[3]);
    }
}

// ---------------- K-stats: BN batch stats from g_t ----------------
__global__ void k_stats(int Nx) {
    __shared__ float sS[64], sQ[64];
    int tid = threadIdx.x;
    if (tid < 64) { sS[tid] = 0.f; sQ[tid] = 0.f; }
    __syncthreads();
    int cc = tid & 15;
    float4 s = make_float4(0.f, 0.f, 0.f, 0.f);
    float4 q = make_float4(0.f, 0.f, 0.f, 0.f);
    for (int r = blockIdx.x * 16 + (tid >> 4); r < Nx; r += gridDim.x * 16) {
        float4 v = reinterpret_cast<const float4*>(g_t)[(size_t)r * 16 + cc];
        s.x += v.x; s.y += v.y; s.z += v.z; s.w += v.w;
        q.x += v.x * v.x; q.y += v.y * v.y; q.z += v.z * v.z; q.w += v.w * v.w;
    }
    int c0 = cc * 4;
    atomicAdd(&sS[c0], s.x); atomicAdd(&sS[c0 + 1], s.y);
    atomicAdd(&sS[c0 + 2], s.z); atomicAdd(&sS[c0 + 3], s.w);
    atomicAdd(&sQ[c0], q.x); atomicAdd(&sQ[c0 + 1], q.y);
    atomicAdd(&sQ[c0 + 2], q.z); atomicAdd(&sQ[c0 + 3], q.w);
    __syncthreads();
    if (tid < 64) {
        atomicAdd(&g_sum[tid], (double)sS[tid]);
        atomicAdd(&g_sumsq[tid], (double)sQ[tid]);
    }
}

// ---------------- K4: BN + ReLU + lin2 + h_update, thread-per-row ------
__global__ void __launch_bounds__(256) k_lin2(
    const float* __restrict__ gamma, const float* __restrict__ beta,
    const float* __restrict__ W2, const float* __restrict__ b2,
    int Nx, int Nold) {
    __shared__ float sW[4096];
    __shared__ float sB[64];
    __shared__ float sScale[64], sShift[64];
    int tid = threadIdx.x;
    for (int t = tid; t < 4096; t += 256) sW[t] = W2[t];
    if (tid < 64) {
        sB[tid] = b2[tid];
        double mu = g_sum[tid] / (double)Nx;
        double var = g_sumsq[tid] / (double)Nx - mu * mu;
        float inv = rsqrtf((float)var + BN_EPS);
        float sc = gamma[tid] * inv;
        sScale[tid] = sc;
        sShift[tid] = beta[tid] - (float)mu * sc;
    }
    __syncthreads();
    int i = blockIdx.x * 256 + tid;
    if (i >= Nx) return;
    u64 x2[32];
    const float4* tr = reinterpret_cast<const float4*>(g_t + (size_t)i * NHID);
#pragma unroll
    for (int k = 0; k < 16; k++) {
        float4 v = tr[k];
        int k0 = k * 4;
        v.x = fmaxf(v.x * sScale[k0] + sShift[k0], 0.f);
        v.y = fmaxf(v.y * sScale[k0 + 1] + sShift[k0 + 1], 0.f);
        v.z = fmaxf(v.z * sScale[k0 + 2] + sShift[k0 + 2], 0.f);
        v.w = fmaxf(v.w * sScale[k0 + 3] + sShift[k0 + 3], 0.f);
        x2[2 * k] = pack2(v.x, v.y);
        x2[2 * k + 1] = pack2(v.z, v.w);
    }
    float dn = g_dn[Nold + i];
    float4* o = reinterpret_cast<float4*>(g_h + (size_t)(Nold + i) * NHID);
    for (int jg = 0; jg < 16; jg++) {
        float res[4];
#pragma unroll
        for (int jj = 0; jj < 4; jj++) {
            int j = jg * 4 + jj;
            u64 acc = pack2(sB[j], 0.f);
            const ulonglong2* wr = reinterpret_cast<const ulonglong2*>(sW + j * 64);
#pragma unroll
            for (int k = 0; k < 16; k++) {
                ulonglong2 wv = wr[k];
                fma2(acc, x2[2 * k], wv.x);
                fma2(acc, x2[2 * k + 1], wv.y);
            }
            float2 p = unpack2(acc);
            res[jj] = (p.x + p.y) * dn;
        }
        o[jg] = make_float4(res[0], res[1], res[2], res[3]);
    }
}

// ---------------- K6: persistent single-phase dual-weight GRU + heads --
#define SMG_BIAS 49152
#define SMG_WON  (SMG_BIAS + 768)
#define SMG_WOE  (SMG_WON + 64)
#define SMG_TOT  (SMG_WOE + 64)

__global__ void __launch_bounds__(256) k_gru(
    const float* __restrict__ Wi_n, const float* __restrict__ bi_n,
    const float* __restrict__ Wh_n, const float* __restrict__ bh_n,
    const float* __restrict__ Wi_e, const float* __restrict__ bi_e,
    const float* __restrict__ Wh_e, const float* __restrict__ bh_e,
    const float* __restrict__ w_on, const float* __restrict__ b_on,
    const float* __restrict__ w_oe, const float* __restrict__ b_oe,
    int N, float* __restrict__ out) {
    extern __shared__ float sm[];
    int tid = threadIdx.x;
    {
        float4* s4 = reinterpret_cast<float4*>(sm);
        const float4* a0 = reinterpret_cast<const float4*>(Wi_n);
        const float4* a1 = reinterpret_cast<const float4*>(Wh_n);
        const float4* a2 = reinterpret_cast<const float4*>(Wi_e);
        const float4* a3 = reinterpret_cast<const float4*>(Wh_e);
        for (int t = tid; t < 3072; t += 256) {
            s4[t] = a0[t];
            s4[3072 + t] = a1[t];
            s4[6144 + t] = a2[t];
            s4[9216 + t] = a3[t];
        }
        if (tid < 192) {
            sm[SMG_BIAS + tid] = bi_n[tid];
            sm[SMG_BIAS + 192 + tid] = bh_n[tid];
            sm[SMG_BIAS + 384 + tid] = bi_e[tid];
            sm[SMG_BIAS + 576 + tid] = bh_e[tid];
        }
        if (tid < 64) {
            sm[SMG_WON + tid] = w_on[tid];
            sm[SMG_WOE + tid] = w_oe[tid];
        }
    }
    __syncthreads();

    int wid = tid >> 5, lane = tid & 31;
    bool isNode = wid < 4;
    int local = isNode ? 2 * (wid * 32 + lane) : 2 * ((wid - 4) * 32 + lane) + 1;
    const float* mptr = isNode ? g_mn : g_me;
    const float* optr = isNode ? g_me : g_mn;
    const float* sWi = sm + (isNode ? 0 : 24576);
    const float* sWh = sWi + 12288;
    const float* sBi = sm + SMG_BIAS + (isNode ? 0 : 384);
    const float* sBh = sBi + 192;
    const float* oWi = sm + (isNode ? 24576 : 0);
    const float* oWh = oWi + 12288;
    const float* oBi = sm + SMG_BIAS + (isNode ? 384 : 0);
    const float* oBh = oBi + 192;
    const float* sWon = sm + SMG_WON;
    const float* sWoe = sm + SMG_WOE;
    float* out_h = out + 2 * (size_t)N;
    float bon = b_on[0], boe = b_oe[0];

    u64 m2[32], h2[32];
    float hl[64];

    for (int base = blockIdx.x * 256; base < N; base += gridDim.x * 256) {
        int i = base + local;
        bool active = i < N;

        float dn_i = 0.f, de_i = 0.f;
        if (active) { dn_i = g_dn[i]; de_i = g_de[i]; }
        float scale  = isNode ? dn_i : de_i;
        float oscale = isNode ? de_i : dn_i;

        if (active) {
            const float4* h4 = reinterpret_cast<const float4*>(g_h + (size_t)i * NHID);
#pragma unroll
            for (int k = 0; k < 16; k++) {
                float4 a = h4[k];
                hl[4 * k] = a.x; hl[4 * k + 1] = a.y; hl[4 * k + 2] = a.z; hl[4 * k + 3] = a.w;
                h2[2 * k] = pack2(a.x, a.y);
                h2[2 * k + 1] = pack2(a.z, a.w);
            }
        }
        float s_on = 0.f, s_oe = 0.f;

        bool did_main = active && (scale != 0.f);
        if (did_main) {
            const ulonglong2* mm = reinterpret_cast<const ulonglong2*>(mptr + (size_t)i * NHID);
#pragma unroll
            for (int k = 0; k < 16; k++) {
                ulonglong2 mv = mm[k];
                m2[2 * k] = mv.x; m2[2 * k + 1] = mv.y;
            }
            for (int j = 0; j < NHID; j++) {
                u64 a_r = pack2(sBi[j], 0.f);
                u64 a_z = pack2(sBi[64 + j], 0.f);
                u64 a_n = pack2(sBi[128 + j], 0.f);
                u64 b_r = pack2(sBh[j], 0.f);
                u64 b_z = pack2(sBh[64 + j], 0.f);
                u64 b_n = pack2(sBh[128 + j], 0.f);
                const ulonglong2* w0 = reinterpret_cast<const ulonglong2*>(sWi + j * 64);
                const ulonglong2* w1 = reinterpret_cast<const ulonglong2*>(sWi + (64 + j) * 64);
                const ulonglong2* w2 = reinterpret_cast<const ulonglong2*>(sWi + (128 + j) * 64);
                const ulonglong2* v0 = reinterpret_cast<const ulonglong2*>(sWh + j * 64);
                const ulonglong2* v1 = reinterpret_cast<const ulonglong2*>(sWh + (64 + j) * 64);
                const ulonglong2* v2 = reinterpret_cast<const ulonglong2*>(sWh + (128 + j) * 64);
#pragma unroll
                for (int kk = 0; kk < 16; kk++) {
                    ulonglong2 W0 = w0[kk], W1 = w1[kk], W2 = w2[kk];
                    ulonglong2 V0 = v0[kk], V1 = v1[kk], V2 = v2[kk];
                    u64 ma = m2[2 * kk], mb = m2[2 * kk + 1];
                    u64 ha = h2[2 * kk], hb = h2[2 * kk + 1];
                    fma2(a_r, ma, W0.x); fma2(a_r, mb, W0.y);
                    fma2(a_z, ma, W1.x); fma2(a_z, mb, W1.y);
                    fma2(a_n, ma, W2.x); fma2(a_n, mb, W2.y);
                    fma2(b_r, ha, V0.x); fma2(b_r, hb, V0.y);
                    fma2(b_z, ha, V1.x); fma2(b_z, hb, V1.y);
                    fma2(b_n, ha, V2.x); fma2(b_n, hb, V2.y);
                }
                float2 pr = unpack2(a_r), pz = unpack2(a_z), pn = unpack2(a_n);
                float2 qr = unpack2(b_r), qz = unpack2(b_z), qn = unpack2(b_n);
                float r = sigmf(pr.x + pr.y + qr.x + qr.y);
                float z = sigmf(pz.x + pz.y + qz.x + qz.y);
                float ng = tanhfast(pn.x + pn.y + r * (qn.x + qn.y));
                float hv = (1.f - z) * ng + z * hl[j];
                float hf = scale * hv;
                out_h[(size_t)i * NHID + j] = hf;
                s_on += hf * sWon[j];
                s_oe += hf * sWoe[j];
            }
        } else if (active) {
            float4 z4 = make_float4(0.f, 0.f, 0.f, 0.f);
            float4* o4 = reinterpret_cast<float4*>(out_h + (size_t)i * NHID);
#pragma unroll
            for (int k = 0; k < 16; k++) o4[k] = z4;
        }

        bool need2 = active && (oscale != 0.f);
        if (need2) {
            s_on = 0.f; s_oe = 0.f;
            const ulonglong2* mm = reinterpret_cast<const ulonglong2*>(optr + (size_t)i * NHID);
#pragma unroll
            for (int k = 0; k < 16; k++) {
                ulonglong2 mv = mm[k];
                m2[2 * k] = mv.x; m2[2 * k + 1] = mv.y;
            }
            for (int j = 0; j < NHID; j++) {
                u64 a_r = pack2(oBi[j], 0.f);
                u64 a_z = pack2(oBi[64 + j], 0.f);
                u64 a_n = pack2(oBi[128 + j], 0.f);
                u64 b_r = pack2(oBh[j], 0.f);
                u64 b_z = pack2(oBh[64 + j], 0.f);
                u64 b_n = pack2(oBh[128 + j], 0.f);
                const ulonglong2* w0 = reinterpret_cast<const ulonglong2*>(oWi + j * 64);
                const ulonglong2* w1 = reinterpret_cast<const ulonglong2*>(oWi + (64 + j) * 64);
                const ulonglong2* w2 = reinterpret_cast<const ulonglong2*>(oWi + (128 + j) * 64);
                const ulonglong2* v0 = reinterpret_cast<const ulonglong2*>(oWh + j * 64);
                const ulonglong2* v1 = reinterpret_cast<const ulonglong2*>(oWh + (64 + j) * 64);
                const ulonglong2* v2 = reinterpret_cast<const ulonglong2*>(oWh + (128 + j) * 64);
#pragma unroll
                for (int kk = 0; kk < 16; kk++) {
                    ulonglong2 W0 = w0[kk], W1 = w1[kk], W2 = w2[kk];
                    ulonglong2 V0 = v0[kk], V1 = v1[kk], V2 = v2[kk];
                    u64 ma = m2[2 * kk], mb = m2[2 * kk + 1];
                    u64 ha = h2[2 * kk], hb = h2[2 * kk + 1];
                    fma2(a_r, ma, W0.x); fma2(a_r, mb, W0.y);
                    fma2(a_z, ma, W1.x); fma2(a_z, mb, W1.y);
                    fma2(a_n, ma, W2.x); fma2(a_n, mb, W2.y);
                    fma2(b_r, ha, V0.x); fma2(b_r, hb, V0.y);
                    fma2(b_z, ha, V1.x); fma2(b_z, hb, V1.y);
                    fma2(b_n, ha, V2.x); fma2(b_n, hb, V2.y);
                }
                float2 pr = unpack2(a_r), pz = unpack2(a_z), pn = unpack2(a_n);
                float2 qr = unpack2(b_r), qz = unpack2(b_z), qn = unpack2(b_n);
                float r = sigmf(pr.x + pr.y + qr.x + qr.y);
                float z = sigmf(pz.x + pz.y + qz.x + qz.y);
                float ng = tanhfast(pn.x + pn.y + r * (qn.x + qn.y));
                float hv = (1.f - z) * ng + z * hl[j];
                size_t oi = (size_t)i * NHID + j;
                float hf = out_h[oi] + oscale * hv;
                out_h[oi] = hf;
                s_on += hf * sWon[j];
                s_oe += hf * sWoe[j];
            }
        }

        if (active) {
            float y = dn_i * (s_on + bon) + de_i * (s_oe + boe);
            out[i] = sigmf(y);
            out[(size_t)N + i] = y;
        }
    }
}

// ---------------- launch ----------------
extern "C" void kernel_launch(void* const* d_in, const int* in_sizes, int n_in,
                              void* d_out, int out_size) {
    const float* x     = (const float*)d_in[0];
    const float* h_in  = (const float*)d_in[1];
    const int*   nr    = (const int*)d_in[2];
    const int*   nc    = (const int*)d_in[3];
    const float* nv    = (const float*)d_in[4];
    const int*   er    = (const int*)d_in[5];
    const int*   ec    = (const int*)d_in[6];
    const float* ev    = (const float*)d_in[7];
    const float* W1    = (const float*)d_in[8];
    const float* b1    = (const float*)d_in[9];
    const float* gamma = (const float*)d_in[10];
    const float* beta  = (const float*)d_in[11];
    const float* W2    = (const float*)d_in[12];
    const float* b2    = (const float*)d_in[13];
    const float* Wi_n  = (const float*)d_in[14];
    const float* bi_n  = (const float*)d_in[15];
    const float* Wh_n  = (const float*)d_in[16];
    const float* bh_n  = (const float*)d_in[17];
    const float* Wi_e  = (const float*)d_in[18];
    const float* bi_e  = (const float*)d_in[19];
    const float* Wh_e  = (const float*)d_in[20];
    const float* bh_e  = (const float*)d_in[21];
    const float* w_on  = (const float*)d_in[22];
    const float* b_on  = (const float*)d_in[23];
    const float* w_oe  = (const float*)d_in[24];
    const float* b_oe  = (const float*)d_in[25];

    int Nx   = in_sizes[0] / NHID;
    int Nold = in_sizes[1] / NHID;
    int N    = Nx + Nold;
    int nnzN = in_sizes[2];
    int nnzE = in_sizes[5];
    float* out = (float*)d_out;

    cudaFuncSetAttribute(k_gru, cudaFuncAttributeMaxDynamicSharedMemorySize,
                         SMG_TOT * sizeof(float));

    k_init<<<1024, 256>>>((const float4*)h_in, Nold * (NHID / 4), N);
    k_hist<<<1024, 256>>>(nr, nc, nv, nnzN, er, ec, ev, nnzE);

    k_lin1<<<(Nx + 255) / 256, 256>>>(x, W1, b1, Nx);
    k_stats<<<256, 256>>>(Nx);
    k_lin2<<<(Nx + 255) / 256, 256>>>(gamma, beta, W2, b2, Nx, Nold);

    int nblk = (N + 4095) / 4096;
    {
        dim3 g1(nblk, 2);
        k_scan1<<<g1, 256>>>(N);
        k_scan2<<<2, 256>>>(nblk);
        dim3 g3(256, 2);
        k_scan3<<<g3, 256>>>(N);
    }

    k_scatter<<<1024, 256>>>(nr, nc, nv, nnzN, er, ec, ev, nnzE);

    {
        long long warps = 2LL * N;
        int blocks = (int)((warps * 32 + 255) / 256);
        k_spmm_csr<<<blocks, 256>>>(N);
    }

    k_gru<<<NSM, 256, SMG_TOT * sizeof(float)>>>(
        Wi_n, bi_n, Wh_n, bh_n, Wi_e, bi_e, Wh_e, bh_e,
        w_on, b_on, w_oe, b_oe, N, out);
}

// round 7
// speedup vs baseline: 3.4681x; 1.0506x over previous
#include <cuda_runtime.h>
#include <math.h>

#define NHID 64
#define NMAX 400000
#define NXMAX 100000
#define NNZCAP 2200000
#define BN_EPS 1e-5f
#define NSM 148

typedef unsigned long long u64;

// ---------------- scratch (device globals; no allocations) ----------------
__device__ __align__(256) float  g_dn[NMAX];
__device__ __align__(256) float  g_de[NMAX];
__device__ __align__(256) float  g_h [NMAX * NHID];
__device__ __align__(256) float  g_mn[NMAX * NHID];
__device__ __align__(256) float  g_me[NMAX * NHID];
__device__ __align__(256) float  g_t [NXMAX * NHID];
__device__ double g_sum[NHID];
__device__ double g_sumsq[NHID];
// CSR build scratch
__device__ __align__(256) int   g_cnt_n[NMAX], g_cnt_e[NMAX];
__device__ __align__(256) int   g_cur_n[NMAX], g_cur_e[NMAX];
__device__ __align__(256) int   g_start_n[NMAX], g_start_e[NMAX];
__device__ __align__(256) int2  g_pkn[NNZCAP], g_pke[NNZCAP];
__device__ int g_bsum_n[4096], g_bsum_e[4096], g_boff_n[4096], g_boff_e[4096];

// ---------------- packed f32x2 helpers ----------------
__device__ __forceinline__ u64 pack2(float lo, float hi) {
    u64 r; asm("mov.b64 %0, {%1,%2};" : "=l"(r) : "f"(lo), "f"(hi)); return r;
}
__device__ __forceinline__ float2 unpack2(u64 v) {
    float2 r; asm("mov.b64 {%0,%1}, %2;" : "=f"(r.x), "=f"(r.y) : "l"(v)); return r;
}
__device__ __forceinline__ void fma2(u64& acc, u64 a, u64 b) {
    asm("fma.rn.f32x2 %0, %1, %2, %0;" : "+l"(acc) : "l"(a), "l"(b));
}
__device__ __forceinline__ float sigmf(float x) {
    return __fdividef(1.0f, 1.0f + __expf(-x));
}
__device__ __forceinline__ float tanhfast(float x) {
    return 2.0f * sigmf(2.0f * x) - 1.0f;
}

// ---------------- K0: zero scratch + copy h_in (merged) ----------------
__global__ void k_init(const float4* __restrict__ h_src, int n4, int N) {
    int i = blockIdx.x * blockDim.x + threadIdx.x;
    int stride = gridDim.x * blockDim.x;
    float4* dst = reinterpret_cast<float4*>(g_h);
    for (int j = i; j < n4; j += stride) dst[j] = h_src[j];
    for (int j = i; j < N; j += stride) {
        g_dn[j] = 0.f; g_de[j] = 0.f;
        g_cnt_n[j] = 0; g_cnt_e[j] = 0;
        g_cur_n[j] = 0; g_cur_e[j] = 0;
    }
    if (i < NHID) { g_sum[i] = 0.0; g_sumsq[i] = 0.0; }
}

// ---------------- K1: histogram + diagonal extraction (1 entry/thread) -
__global__ void k_hist(const int* __restrict__ nr, const int* __restrict__ nc,
                       const float* __restrict__ nv, int nnzN,
                       const int* __restrict__ er, const int* __restrict__ ec,
                       const float* __restrict__ ev, int nnzE) {
    int j = blockIdx.x * blockDim.x + threadIdx.x;
    int tot = nnzN + nnzE;
    if (j >= tot) return;
    if (j < nnzN) {
        int r = nr[j], c = nc[j];
        if (r == c) atomicAdd(&g_dn[r], nv[j]);
        else atomicAdd(&g_cnt_n[r], 1);
    } else {
        int e = j - nnzN;
        int r = er[e], c = ec[e];
        if (r == c) atomicAdd(&g_de[r], ev[e]);
        else atomicAdd(&g_cnt_e[r], 1);
    }
}

// ---------------- scans (blockIdx.y: 0=node, 1=edge) ----------------
__global__ void k_scan1(int n) {
    int edge = blockIdx.y;
    const int* in = edge ? g_cnt_e : g_cnt_n;
    int* out = edge ? g_start_e : g_start_n;
    int* bsum = edge ? g_bsum_e : g_bsum_n;
    __shared__ int sh[256];
    int tid = threadIdx.x;
    int base = blockIdx.x * 4096 + tid * 16;
    int loc[16]; int s = 0;
#pragma unroll
    for (int k = 0; k < 16; k++) {
        loc[k] = (base + k < n) ? in[base + k] : 0;
        s += loc[k];
    }
    sh[tid] = s; __syncthreads();
    for (int off = 1; off < 256; off <<= 1) {
        int t2 = (tid >= off) ? sh[tid - off] : 0;
        __syncthreads();
        sh[tid] += t2;
        __syncthreads();
    }
    int incl = sh[tid];
    int run = incl - s;
#pragma unroll
    for (int k = 0; k < 16; k++) {
        if (base + k < n) out[base + k] = run;
        run += loc[k];
    }
    if (tid == 255) bsum[blockIdx.x] = incl;
}

__global__ void k_scan2(int nblk) {
    int edge = blockIdx.x;
    const int* bsum = edge ? g_bsum_e : g_bsum_n;
    int* boff = edge ? g_boff_e : g_boff_n;
    __shared__ int sh[256];
    int tid = threadIdx.x;
    int base = tid * 16;
    int loc[16]; int s = 0;
#pragma unroll
    for (int k = 0; k < 16; k++) {
        loc[k] = (base + k < nblk) ? bsum[base + k] : 0;
        s += loc[k];
    }
    sh[tid] = s; __syncthreads();
    for (int off = 1; off < 256; off <<= 1) {
        int t2 = (tid >= off) ? sh[tid - off] : 0;
        __syncthreads();
        sh[tid] += t2;
        __syncthreads();
    }
    int incl = sh[tid];
    int run = incl - s;
#pragma unroll
    for (int k = 0; k < 16; k++) {
        if (base + k < nblk) boff[base + k] = run;
        run += loc[k];
    }
}

__global__ void k_scan3(int n) {
    int edge = blockIdx.y;
    int* out = edge ? g_start_e : g_start_n;
    const int* boff = edge ? g_boff_e : g_boff_n;
    int i = blockIdx.x * blockDim.x + threadIdx.x;
    int stride = gridDim.x * blockDim.x;
    for (int j = i; j < n; j += stride) out[j] += boff[j >> 12];
}

// ---------------- K-scatter: build packed CSR, filtered (1 entry/thread)
__global__ void k_scatter(const int* __restrict__ nr, const int* __restrict__ nc,
                          const float* __restrict__ nv, int nnzN,
                          const int* __restrict__ er, const int* __restrict__ ec,
                          const float* __restrict__ ev, int nnzE) {
    int j = blockIdx.x * blockDim.x + threadIdx.x;
    int tot = nnzN + nnzE;
    if (j >= tot) return;
    if (j < nnzN) {
        int r = nr[j], c = nc[j];
        if (r != c && g_dn[r] != 0.f) {
            int p = g_start_n[r] + atomicAdd(&g_cur_n[r], 1);
            g_pkn[p] = make_int2(c, __float_as_int(nv[j]));
        }
    } else {
        int e = j - nnzN;
        int r = er[e], c = ec[e];
        if (r != c && g_de[r] != 0.f) {
            int p = g_start_e[r] + atomicAdd(&g_cur_e[r], 1);
            g_pke[p] = make_int2(c, __float_as_int(ev[e]));
        }
    }
}

// ---------------- K-spmm CSR: warp per row, 16-lane float4, 2 entries/it
__global__ void k_spmm_csr(int N) {
    int w = (blockIdx.x * blockDim.x + threadIdx.x) >> 5;
    int lane = threadIdx.x & 31;
    if (w >= 2 * N) return;
    bool node = w < N;
    int r = node ? w : w - N;
    float scale = node ? g_dn[r] : g_de[r];
    if (scale == 0.f) return;   // row never consumed
    const int2* pk = node ? g_pkn : g_pke;
    int s = node ? g_start_n[r] : g_start_e[r];
    int cnt = node ? g_cur_n[r] : g_cur_e[r];
    int half = lane >> 4;       // which of 2 concurrent entries
    int l16 = lane & 15;
    float4 acc = make_float4(0.f, 0.f, 0.f, 0.f);
    int p = s, e = s + cnt;
    for (; p + 4 <= e; p += 4) {
        int2 ea = pk[p + half];
        int2 eb = pk[p + 2 + half];
        float4 ha = reinterpret_cast<const float4*>(g_h + (size_t)ea.x * NHID)[l16];
        float4 hb = reinterpret_cast<const float4*>(g_h + (size_t)eb.x * NHID)[l16];
        float va = __int_as_float(ea.y), vb = __int_as_float(eb.y);
        acc.x += va * ha.x + vb * hb.x;
        acc.y += va * ha.y + vb * hb.y;
        acc.z += va * ha.z + vb * hb.z;
        acc.w += va * ha.w + vb * hb.w;
    }
    if (p + 2 <= e) {
        int2 ea = pk[p + half];
        float4 ha = reinterpret_cast<const float4*>(g_h + (size_t)ea.x * NHID)[l16];
        float va = __int_as_float(ea.y);
        acc.x += va * ha.x; acc.y += va * ha.y;
        acc.z += va * ha.z; acc.w += va * ha.w;
        p += 2;
    }
    if (p < e && half == 0) {
        int2 ea = pk[p];
        float4 ha = reinterpret_cast<const float4*>(g_h + (size_t)ea.x * NHID)[l16];
        float va = __int_as_float(ea.y);
        acc.x += va * ha.x; acc.y += va * ha.y;
        acc.z += va * ha.z; acc.w += va * ha.w;
    }
    // combine the two halves
    acc.x += __shfl_xor_sync(0xffffffffu, acc.x, 16);
    acc.y += __shfl_xor_sync(0xffffffffu, acc.y, 16);
    acc.z += __shfl_xor_sync(0xffffffffu, acc.z, 16);
    acc.w += __shfl_xor_sync(0xffffffffu, acc.w, 16);
    if (half == 0) {
        float* M = node ? g_mn : g_me;
        reinterpret_cast<float4*>(M + (size_t)r * NHID)[l16] = acc;
    }
}

// ---------------- K3: lin1, thread-per-row ----------------
__global__ void __launch_bounds__(256) k_lin1(
    const float* __restrict__ x, const float* __restrict__ W1,
    const float* __restrict__ b1, int Nx) {
    __shared__ float sW[4096];
    __shared__ float sB[64];
    int tid = threadIdx.x;
    for (int t = tid; t < 4096; t += 256) sW[t] = W1[t];
    if (tid < 64) sB[tid] = b1[tid];
    __syncthreads();
    int i = blockIdx.x * 256 + tid;
    if (i >= Nx) return;
    u64 x2[32];
    const ulonglong2* xr = reinterpret_cast<const ulonglong2*>(x + (size_t)i * NHID);
#pragma unroll
    for (int k = 0; k < 16; k++) { ulonglong2 v = xr[k]; x2[2 * k] = v.x; x2[2 * k + 1] = v.y; }
    float4* o = reinterpret_cast<float4*>(g_t + (size_t)i * NHID);
    for (int jg = 0; jg < 16; jg++) {
        float res[4];
#pragma unroll
        for (int jj = 0; jj < 4; jj++) {
            int j = jg * 4 + jj;
            u64 acc = pack2(sB[j], 0.f);
            const ulonglong2* wr = reinterpret_cast<const ulonglong2*>(sW + j * 64);
#pragma unroll
            for (int k = 0; k < 16; k++) {
                ulonglong2 wv = wr[k];
                fma2(acc, x2[2 * k], wv.x);
                fma2(acc, x2[2 * k + 1], wv.y);
            }
            float2 p = unpack2(acc);
            res[jj] = p.x + p.y;
        }
        o[jg] = make_float4(res[0], res[1], res[2], res[3]);
    }
}

// ---------------- K-stats: BN batch stats from g_t ----------------
__global__ void k_stats(int Nx) {
    __shared__ float sS[64], sQ[64];
    int tid = threadIdx.x;
    if (tid < 64) { sS[tid] = 0.f; sQ[tid] = 0.f; }
    __syncthreads();
    int cc = tid & 15;
    float4 s = make_float4(0.f, 0.f, 0.f, 0.f);
    float4 q = make_float4(0.f, 0.f, 0.f, 0.f);
    for (int r = blockIdx.x * 16 + (tid >> 4); r < Nx; r += gridDim.x * 16) {
        float4 v = reinterpret_cast<const float4*>(g_t)[(size_t)r * 16 + cc];
        s.x += v.x; s.y += v.y; s.z += v.z; s.w += v.w;
        q.x += v.x * v.x; q.y += v.y * v.y; q.z += v.z * v.z; q.w += v.w * v.w;
    }
    int c0 = cc * 4;
    atomicAdd(&sS[c0], s.x); atomicAdd(&sS[c0 + 1], s.y);
    atomicAdd(&sS[c0 + 2], s.z); atomicAdd(&sS[c0 + 3], s.w);
    atomicAdd(&sQ[c0], q.x); atomicAdd(&sQ[c0 + 1], q.y);
    atomicAdd(&sQ[c0 + 2], q.z); atomicAdd(&sQ[c0 + 3], q.w);
    __syncthreads();
    if (tid < 64) {
        atomicAdd(&g_sum[tid], (double)sS[tid]);
        atomicAdd(&g_sumsq[tid], (double)sQ[tid]);
    }
}

// ---------------- K4: BN + ReLU + lin2 + h_update, thread-per-row ------
__global__ void __launch_bounds__(256) k_lin2(
    const float* __restrict__ gamma, const float* __restrict__ beta,
    const float* __restrict__ W2, const float* __restrict__ b2,
    int Nx, int Nold) {
    __shared__ float sW[4096];
    __shared__ float sB[64];
    __shared__ float sScale[64], sShift[64];
    int tid = threadIdx.x;
    for (int t = tid; t < 4096; t += 256) sW[t] = W2[t];
    if (tid < 64) {
        sB[tid] = b2[tid];
        double mu = g_sum[tid] / (double)Nx;
        double var = g_sumsq[tid] / (double)Nx - mu * mu;
        float inv = rsqrtf((float)var + BN_EPS);
        float sc = gamma[tid] * inv;
        sScale[tid] = sc;
        sShift[tid] = beta[tid] - (float)mu * sc;
    }
    __syncthreads();
    int i = blockIdx.x * 256 + tid;
    if (i >= Nx) return;
    u64 x2[32];
    const float4* tr = reinterpret_cast<const float4*>(g_t + (size_t)i * NHID);
#pragma unroll
    for (int k = 0; k < 16; k++) {
        float4 v = tr[k];
        int k0 = k * 4;
        v.x = fmaxf(v.x * sScale[k0] + sShift[k0], 0.f);
        v.y = fmaxf(v.y * sScale[k0 + 1] + sShift[k0 + 1], 0.f);
        v.z = fmaxf(v.z * sScale[k0 + 2] + sShift[k0 + 2], 0.f);
        v.w = fmaxf(v.w * sScale[k0 + 3] + sShift[k0 + 3], 0.f);
        x2[2 * k] = pack2(v.x, v.y);
        x2[2 * k + 1] = pack2(v.z, v.w);
    }
    float dn = g_dn[Nold + i];
    float4* o = reinterpret_cast<float4*>(g_h + (size_t)(Nold + i) * NHID);
    for (int jg = 0; jg < 16; jg++) {
        float res[4];
#pragma unroll
        for (int jj = 0; jj < 4; jj++) {
            int j = jg * 4 + jj;
            u64 acc = pack2(sB[j], 0.f);
            const ulonglong2* wr = reinterpret_cast<const ulonglong2*>(sW + j * 64);
#pragma unroll
            for (int k = 0; k < 16; k++) {
                ulonglong2 wv = wr[k];
                fma2(acc, x2[2 * k], wv.x);
                fma2(acc, x2[2 * k + 1], wv.y);
            }
            float2 p = unpack2(acc);
            res[jj] = (p.x + p.y) * dn;
        }
        o[jg] = make_float4(res[0], res[1], res[2], res[3]);
    }
}

// ---------------- K6: persistent dual-weight GRU + heads (j-unroll 2) --
#define SMG_BIAS 49152
#define SMG_WON  (SMG_BIAS + 768)
#define SMG_WOE  (SMG_WON + 64)
#define SMG_TOT  (SMG_WOE + 64)

__global__ void __launch_bounds__(256) k_gru(
    const float* __restrict__ Wi_n, const float* __restrict__ bi_n,
    const float* __restrict__ Wh_n, const float* __restrict__ bh_n,
    const float* __restrict__ Wi_e, const float* __restrict__ bi_e,
    const float* __restrict__ Wh_e, const float* __restrict__ bh_e,
    const float* __restrict__ w_on, const float* __restrict__ b_on,
    const float* __restrict__ w_oe, const float* __restrict__ b_oe,
    int N, float* __restrict__ out) {
    extern __shared__ float sm[];
    int tid = threadIdx.x;
    {
        float4* s4 = reinterpret_cast<float4*>(sm);
        const float4* a0 = reinterpret_cast<const float4*>(Wi_n);
        const float4* a1 = reinterpret_cast<const float4*>(Wh_n);
        const float4* a2 = reinterpret_cast<const float4*>(Wi_e);
        const float4* a3 = reinterpret_cast<const float4*>(Wh_e);
        for (int t = tid; t < 3072; t += 256) {
            s4[t] = a0[t];
            s4[3072 + t] = a1[t];
            s4[6144 + t] = a2[t];
            s4[9216 + t] = a3[t];
        }
        if (tid < 192) {
            sm[SMG_BIAS + tid] = bi_n[tid];
            sm[SMG_BIAS + 192 + tid] = bh_n[tid];
            sm[SMG_BIAS + 384 + tid] = bi_e[tid];
            sm[SMG_BIAS + 576 + tid] = bh_e[tid];
        }
        if (tid < 64) {
            sm[SMG_WON + tid] = w_on[tid];
            sm[SMG_WOE + tid] = w_oe[tid];
        }
    }
    __syncthreads();

    int wid = tid >> 5, lane = tid & 31;
    bool isNode = wid < 4;
    int local = isNode ? 2 * (wid * 32 + lane) : 2 * ((wid - 4) * 32 + lane) + 1;
    const float* mptr = isNode ? g_mn : g_me;
    const float* optr = isNode ? g_me : g_mn;
    const float* sWi = sm + (isNode ? 0 : 24576);
    const float* sWh = sWi + 12288;
    const float* sBi = sm + SMG_BIAS + (isNode ? 0 : 384);
    const float* sBh = sBi + 192;
    // fallback (never taken on parity-complementary data): other weights from GLOBAL
    const float* gWi = isNode ? Wi_e : Wi_n;
    const float* gWh = isNode ? Wh_e : Wh_n;
    const float* gBi = isNode ? bi_e : bi_n;
    const float* gBh = isNode ? bh_e : bh_n;
    const float* sWon = sm + SMG_WON;
    const float* sWoe = sm + SMG_WOE;
    float* out_h = out + 2 * (size_t)N;
    float bon = b_on[0], boe = b_oe[0];

    u64 m2[32], h2[32];
    float hl[64];

    for (int base = blockIdx.x * 256; base < N; base += gridDim.x * 256) {
        int i = base + local;
        bool active = i < N;

        float dn_i = 0.f, de_i = 0.f;
        if (active) { dn_i = g_dn[i]; de_i = g_de[i]; }
        float scale  = isNode ? dn_i : de_i;
        float oscale = isNode ? de_i : dn_i;

        if (active) {
            const float4* h4 = reinterpret_cast<const float4*>(g_h + (size_t)i * NHID);
#pragma unroll
            for (int k = 0; k < 16; k++) {
                float4 a = h4[k];
                hl[4 * k] = a.x; hl[4 * k + 1] = a.y; hl[4 * k + 2] = a.z; hl[4 * k + 3] = a.w;
                h2[2 * k] = pack2(a.x, a.y);
                h2[2 * k + 1] = pack2(a.z, a.w);
            }
        }
        float s_on = 0.f, s_oe = 0.f;

        bool did_main = active && (scale != 0.f);
        if (did_main) {
            const ulonglong2* mm = reinterpret_cast<const ulonglong2*>(mptr + (size_t)i * NHID);
#pragma unroll
            for (int k = 0; k < 16; k++) {
                ulonglong2 mv = mm[k];
                m2[2 * k] = mv.x; m2[2 * k + 1] = mv.y;
            }
            for (int jp = 0; jp < 32; jp++) {
                int j0 = 2 * jp, j1 = 2 * jp + 1;
                u64 aR0 = pack2(sBi[j0], 0.f),     aR1 = pack2(sBi[j1], 0.f);
                u64 aZ0 = pack2(sBi[64 + j0], 0.f), aZ1 = pack2(sBi[64 + j1], 0.f);
                u64 aN0 = pack2(sBi[128 + j0], 0.f), aN1 = pack2(sBi[128 + j1], 0.f);
                u64 bR0 = pack2(sBh[j0], 0.f),     bR1 = pack2(sBh[j1], 0.f);
                u64 bZ0 = pack2(sBh[64 + j0], 0.f), bZ1 = pack2(sBh[64 + j1], 0.f);
                u64 bN0 = pack2(sBh[128 + j0], 0.f), bN1 = pack2(sBh[128 + j1], 0.f);
                const ulonglong2* w0 = reinterpret_cast<const ulonglong2*>(sWi + j0 * 64);
                const ulonglong2* w1 = reinterpret_cast<const ulonglong2*>(sWi + (64 + j0) * 64);
                const ulonglong2* w2 = reinterpret_cast<const ulonglong2*>(sWi + (128 + j0) * 64);
                const ulonglong2* v0 = reinterpret_cast<const ulonglong2*>(sWh + j0 * 64);
                const ulonglong2* v1 = reinterpret_cast<const ulonglong2*>(sWh + (64 + j0) * 64);
                const ulonglong2* v2 = reinterpret_cast<const ulonglong2*>(sWh + (128 + j0) * 64);
#pragma unroll
                for (int kk = 0; kk < 16; kk++) {
                    u64 ma = m2[2 * kk], mb = m2[2 * kk + 1];
                    u64 ha = h2[2 * kk], hb = h2[2 * kk + 1];
                    ulonglong2 W0a = w0[kk], W0b = w0[kk + 16];
                    ulonglong2 W1a = w1[kk], W1b = w1[kk + 16];
                    ulonglong2 W2a = w2[kk], W2b = w2[kk + 16];
                    ulonglong2 V0a = v0[kk], V0b = v0[kk + 16];
                    ulonglong2 V1a = v1[kk], V1b = v1[kk + 16];
                    ulonglong2 V2a = v2[kk], V2b = v2[kk + 16];
                    fma2(aR0, ma, W0a.x); fma2(aR0, mb, W0a.y);
                    fma2(aR1, ma, W0b.x); fma2(aR1, mb, W0b.y);
                    fma2(aZ0, ma, W1a.x); fma2(aZ0, mb, W1a.y);
                    fma2(aZ1, ma, W1b.x); fma2(aZ1, mb, W1b.y);
                    fma2(aN0, ma, W2a.x); fma2(aN0, mb, W2a.y);
                    fma2(aN1, ma, W2b.x); fma2(aN1, mb, W2b.y);
                    fma2(bR0, ha, V0a.x); fma2(bR0, hb, V0a.y);
                    fma2(bR1, ha, V0b.x); fma2(bR1, hb, V0b.y);
                    fma2(bZ0, ha, V1a.x); fma2(bZ0, hb, V1a.y);
                    fma2(bZ1, ha, V1b.x); fma2(bZ1, hb, V1b.y);
                    fma2(bN0, ha, V2a.x); fma2(bN0, hb, V2a.y);
                    fma2(bN1, ha, V2b.x); fma2(bN1, hb, V2b.y);
                }
                float2 t;
                t = unpack2(aR0); float pr0 = t.x + t.y;
                t = unpack2(aR1); float pr1 = t.x + t.y;
                t = unpack2(aZ0); float pz0 = t.x + t.y;
                t = unpack2(aZ1); float pz1 = t.x + t.y;
                t = unpack2(aN0); float pn0 = t.x + t.y;
                t = unpack2(aN1); float pn1 = t.x + t.y;
                t = unpack2(bR0); float qr0 = t.x + t.y;
                t = unpack2(bR1); float qr1 = t.x + t.y;
                t = unpack2(bZ0); float qz0 = t.x + t.y;
                t = unpack2(bZ1); float qz1 = t.x + t.y;
                t = unpack2(bN0); float qn0 = t.x + t.y;
                t = unpack2(bN1); float qn1 = t.x + t.y;
                float r0 = sigmf(pr0 + qr0), r1 = sigmf(pr1 + qr1);
                float z0 = sigmf(pz0 + qz0), z1 = sigmf(pz1 + qz1);
                float ng0 = tanhfast(pn0 + r0 * qn0), ng1 = tanhfast(pn1 + r1 * qn1);
                float hf0 = scale * ((1.f - z0) * ng0 + z0 * hl[j0]);
                float hf1 = scale * ((1.f - z1) * ng1 + z1 * hl[j1]);
                reinterpret_cast<float2*>(out_h + (size_t)i * NHID)[jp] = make_float2(hf0, hf1);
                s_on += hf0 * sWon[j0] + hf1 * sWon[j1];
                s_oe += hf0 * sWoe[j0] + hf1 * sWoe[j1];
            }
        } else if (active) {
            float4 z4 = make_float4(0.f, 0.f, 0.f, 0.f);
            float4* o4 = reinterpret_cast<float4*>(out_h + (size_t)i * NHID);
#pragma unroll
            for (int k = 0; k < 16; k++) o4[k] = z4;
        }

        // rare general fallback (both dn,de nonzero) — weights from global
        bool need2 = active && (oscale != 0.f);
        if (need2) {
            s_on = 0.f; s_oe = 0.f;
            const float* mo = optr + (size_t)i * NHID;
            float ml[64];
#pragma unroll
            for (int k = 0; k < 64; k++) ml[k] = mo[k];
            for (int j = 0; j < NHID; j++) {
                float ir = gBi[j], iz = gBi[64 + j], in_ = gBi[128 + j];
                float hr = gBh[j], hz = gBh[64 + j], hn = gBh[128 + j];
                for (int k = 0; k < 64; k++) {
                    ir += ml[k] * gWi[j * 64 + k];
                    iz += ml[k] * gWi[(64 + j) * 64 + k];
                    in_ += ml[k] * gWi[(128 + j) * 64 + k];
                    hr += hl[k] * gWh[j * 64 + k];
                    hz += hl[k] * gWh[(64 + j) * 64 + k];
                    hn += hl[k] * gWh[(128 + j) * 64 + k];
                }
                float r = sigmf(ir + hr);
                float z = sigmf(iz + hz);
                float ng = tanhfast(in_ + r * hn);
                float hv = (1.f - z) * ng + z * hl[j];
                size_t oi = (size_t)i * NHID + j;
                float hf = out_h[oi] + oscale * hv;
                out_h[oi] = hf;
                s_on += hf * sWon[j];
                s_oe += hf * sWoe[j];
            }
        }

        if (active) {
            float y = dn_i * (s_on + bon) + de_i * (s_oe + boe);
            out[i] = sigmf(y);
            out[(size_t)N + i] = y;
        }
    }
}

// ---------------- launch ----------------
extern "C" void kernel_launch(void* const* d_in, const int* in_sizes, int n_in,
                              void* d_out, int out_size) {
    const float* x     = (const float*)d_in[0];
    const float* h_in  = (const float*)d_in[1];
    const int*   nr    = (const int*)d_in[2];
    const int*   nc    = (const int*)d_in[3];
    const float* nv    = (const float*)d_in[4];
    const int*   er    = (const int*)d_in[5];
    const int*   ec    = (const int*)d_in[6];
    const float* ev    = (const float*)d_in[7];
    const float* W1    = (const float*)d_in[8];
    const float* b1    = (const float*)d_in[9];
    const float* gamma = (const float*)d_in[10];
    const float* beta  = (const float*)d_in[11];
    const float* W2    = (const float*)d_in[12];
    const float* b2    = (const float*)d_in[13];
    const float* Wi_n  = (const float*)d_in[14];
    const float* bi_n  = (const float*)d_in[15];
    const float* Wh_n  = (const float*)d_in[16];
    const float* bh_n  = (const float*)d_in[17];
    const float* Wi_e  = (const float*)d_in[18];
    const float* bi_e  = (const float*)d_in[19];
    const float* Wh_e  = (const float*)d_in[20];
    const float* bh_e  = (const float*)d_in[21];
    const float* w_on  = (const float*)d_in[22];
    const float* b_on  = (const float*)d_in[23];
    const float* w_oe  = (const float*)d_in[24];
    const float* b_oe  = (const float*)d_in[25];

    int Nx   = in_sizes[0] / NHID;
    int Nold = in_sizes[1] / NHID;
    int N    = Nx + Nold;
    int nnzN = in_sizes[2];
    int nnzE = in_sizes[5];
    float* out = (float*)d_out;

    cudaFuncSetAttribute(k_gru, cudaFuncAttributeMaxDynamicSharedMemorySize,
                         SMG_TOT * sizeof(float));

    k_init<<<1024, 256>>>((const float4*)h_in, Nold * (NHID / 4), N);

    int tot = nnzN + nnzE;
    k_hist<<<(tot + 255) / 256, 256>>>(nr, nc, nv, nnzN, er, ec, ev, nnzE);

    k_lin1<<<(Nx + 255) / 256, 256>>>(x, W1, b1, Nx);
    k_stats<<<256, 256>>>(Nx);
    k_lin2<<<(Nx + 255) / 256, 256>>>(gamma, beta, W2, b2, Nx, Nold);

    int nblk = (N + 4095) / 4096;
    {
        dim3 g1(nblk, 2);
        k_scan1<<<g1, 256>>>(N);
        k_scan2<<<2, 256>>>(nblk);
        dim3 g3(256, 2);
        k_scan3<<<g3, 256>>>(N);
    }

    k_scatter<<<(tot + 255) / 256, 256>>>(nr, nc, nv, nnzN, er, ec, ev, nnzE);

    {
        long long warps = 2LL * N;
        int blocks = (int)((warps * 32 + 255) / 256);
        k_spmm_csr<<<blocks, 256>>>(N);
    }

    k_gru<<<NSM, 256, SMG_TOT * sizeof(float)>>>(
        Wi_n, bi_n, Wh_n, bh_n, Wi_e, bi_e, Wh_e, bh_e,
        w_on, b_on, w_oe, b_oe, N, out);
}